// round 12
// baseline (speedup 1.0000x reference)
#include <cuda_runtime.h>
#include <cuda_bf16.h>
#include <cuda_fp16.h>
#include <cstdint>

#define NROWS 32768   // B*T
#define DDIM  512
#define HDIM  512
#define MCODES 1024
#define CAND_MAX (1 << 22)
#define SURV_MAX (1 << 20)

// ---------------- scratch (static device allocations; no cudaMalloc) -------
__device__ unsigned g_dmin[NROWS];                 // fkey(min d_approx) per row
__device__ unsigned long long g_best2[NROWS];      // final (fkey(d), col)
__device__ float g_counts[MCODES];
__device__ float g_esq[MCODES];
__device__ float g_xsq[NROWS];
__device__ float g_vqrow[NROWS];
__device__ float g_newc[MCODES];
__device__ int   g_mask_mode;
__device__ int   g_lab_mode;
__device__ int   g_labi[NROWS];
__device__ int   g_cnti[MCODES];
__device__ int   g_off[MCODES];
__device__ int   g_fill[MCODES];
__device__ int   g_rows[NROWS];
__device__ float g_pmax[(size_t)NROWS * 16];
__device__ float g_psum[(size_t)NROWS * 16];
__device__ float g_labv[NROWS];
__device__ float g_xn0[NROWS], g_xn1[NROWS];       // norms of scaled splits
__device__ float g_en0[MCODES], g_en1[MCODES];
__device__ unsigned g_en0max, g_en1max, g_dummy0, g_dummy1;
__device__ int   g_ncand, g_nsurv;
__device__ unsigned g_cand[CAND_MAX];
__device__ float    g_cdist[CAND_MAX];
__device__ unsigned g_surv[SURV_MAX];
__device__ __align__(16) __half g_xs[(size_t)NROWS * 1024];    // 16*x split
__device__ __align__(16) __half g_es[(size_t)MCODES * 1024];   // 4096*e split
__device__ __align__(16) __nv_bfloat16 g_a1b[(size_t)NROWS * DDIM];
__device__ __align__(16) __nv_bfloat16 g_a2b[(size_t)NROWS * HDIM];
__device__ __align__(16) __nv_bfloat16 g_hb[(size_t)NROWS * HDIM];
__device__ __align__(16) __nv_bfloat16 g_w1t[(size_t)HDIM * DDIM];
__device__ __align__(16) __nv_bfloat16 g_w2t[(size_t)MCODES * HDIM];

// ---------------- reduction helpers ----------------------------------------
__device__ __forceinline__ float warpReduceSum(float v) {
#pragma unroll
    for (int o = 16; o > 0; o >>= 1) v += __shfl_down_sync(0xffffffffu, v, o);
    return v;
}
__device__ __forceinline__ float blockReduceSum(float v) {
    __shared__ float s[32];
    __syncthreads();
    v = warpReduceSum(v);
    int lane = threadIdx.x & 31, w = threadIdx.x >> 5;
    if (lane == 0) s[w] = v;
    __syncthreads();
    int nw = blockDim.x >> 5;
    float r = (threadIdx.x < nw) ? s[threadIdx.x] : 0.f;
    if (w == 0) { r = warpReduceSum(r); if (lane == 0) s[0] = r; }
    __syncthreads();
    return s[0];
}
__device__ __forceinline__ unsigned fkey(float f) {
    unsigned u = __float_as_uint(f);
    return (u & 0x80000000u) ? ~u : (u | 0x80000000u);
}
__device__ __forceinline__ float inv_fkey(unsigned u) {
    return __uint_as_float((u & 0x80000000u) ? (u ^ 0x80000000u) : ~u);
}
__device__ __forceinline__ uint32_t smem_addr_u32(const void* p) {
    return (uint32_t)__cvta_generic_to_shared(p);
}

// ---------------- init ------------------------------------------------------
__global__ void init_kernel() {
    int i = blockIdx.x * blockDim.x + threadIdx.x;   // grid covers 32768
    g_dmin[i] = 0xFFFFFFFFu;
    g_best2[i] = ~0ull;
    if (i < MCODES) { g_cnti[i] = 0; g_fill[i] = 0; }
    if (i == 0) {
        g_ncand = 0; g_nsurv = 0;
        g_en0max = 0; g_en1max = 0; g_dummy0 = 0; g_dummy1 = 0;
    }
}

// Strict sequential fp32 sum of squares per row (reference rounding order).
__global__ void seqsq_kernel(const float* __restrict__ X, float* __restrict__ out) {
    __shared__ float row[DDIM];
    const float4* src = (const float4*)(X + (size_t)blockIdx.x * DDIM);
    ((float4*)row)[threadIdx.x] = src[threadIdx.x];
    __syncthreads();
    if (threadIdx.x == 0) {
        float s = 0.f;
#pragma unroll 8
        for (int i = 0; i < DDIM; i++)
            s = __fadd_rn(s, __fmul_rn(row[i], row[i]));
        out[blockIdx.x] = s;
    }
}

// 2-way fp16 split of scale*v, vectorized: 4 elems per thread
__global__ void split2_kernel(const float4* __restrict__ V,
                              __half* __restrict__ S, float scale)
{
    int i = blockIdx.x * 256 + threadIdx.x;
    int row = i >> 7, c4 = i & 127;
    float4 v = V[i];
    struct __align__(8) H4 { __half h[4]; } h0, h1;
    float vv[4] = {v.x * scale, v.y * scale, v.z * scale, v.w * scale};
#pragma unroll
    for (int k = 0; k < 4; k++) {
        __half a = __float2half_rn(vv[k]);
        h0.h[k] = a;
        h1.h[k] = __float2half_rn(vv[k] - __half2float(a));
    }
    size_t base = (size_t)row * 1024 + c4 * 4;
    *(uint2*)(S + base)       = *(uint2*)&h0;
    *(uint2*)(S + base + 512) = *(uint2*)&h1;
}

// per-row L2 norms of the two split halves (scaled domain) + global maxes
__global__ void norm2_kernel(const __half* __restrict__ S,
                             float* __restrict__ n0, float* __restrict__ n1,
                             unsigned* __restrict__ mx0, unsigned* __restrict__ mx1)
{
    int row = blockIdx.x;
    const __half* p = S + (size_t)row * 1024;
    float s0 = 0.f, s1 = 0.f;
#pragma unroll
    for (int i = 0; i < 2; i++) {
        float a = __half2float(p[threadIdx.x + i * 256]);
        float b = __half2float(p[512 + threadIdx.x + i * 256]);
        s0 += a * a;
        s1 += b * b;
    }
    s0 = blockReduceSum(s0);
    s1 = blockReduceSum(s1);
    if (threadIdx.x == 0) {
        float v0 = sqrtf(s0), v1 = sqrtf(s1);
        n0[row] = v0;
        n1[row] = v1;
        atomicMax(mx0, __float_as_uint(v0));
        atomicMax(mx1, __float_as_uint(v1));
    }
}

// ---------------- mma / cp.async helpers ------------------------------------
template<bool USE_HALF>
__device__ __forceinline__ void mma16816t(float* d, const uint32_t* a,
                                          const uint32_t* b) {
    if (USE_HALF)
        asm volatile(
            "mma.sync.aligned.m16n8k16.row.col.f32.f16.f16.f32 "
            "{%0,%1,%2,%3}, {%4,%5,%6,%7}, {%8,%9}, {%0,%1,%2,%3};"
            : "+f"(d[0]), "+f"(d[1]), "+f"(d[2]), "+f"(d[3])
            : "r"(a[0]), "r"(a[1]), "r"(a[2]), "r"(a[3]), "r"(b[0]), "r"(b[1]));
    else
        asm volatile(
            "mma.sync.aligned.m16n8k16.row.col.f32.bf16.bf16.f32 "
            "{%0,%1,%2,%3}, {%4,%5,%6,%7}, {%8,%9}, {%0,%1,%2,%3};"
            : "+f"(d[0]), "+f"(d[1]), "+f"(d[2]), "+f"(d[3])
            : "r"(a[0]), "r"(a[1]), "r"(a[2]), "r"(a[3]), "r"(b[0]), "r"(b[1]));
}

__device__ __forceinline__ void cpasync16(uint32_t dst, const void* src) {
    asm volatile("cp.async.cg.shared.global [%0], [%1], 16;"
                 :: "r"(dst), "l"(src) : "memory");
}

__device__ __forceinline__ uint32_t swoff(int r, int c) {
    return ((uint32_t)(r >> 1) << 7) |
           ((uint32_t)((((r & 1) << 2) | c) ^ ((r >> 1) & 7)) << 4);
}

#define STAGE_BYTES 24576u

__device__ __forceinline__ void tcg_load(
    const uint16_t* A, int ldA, const uint16_t* B, int ldB,
    int rowBase, int colBase, uint32_t sbase, int st, int it, int tid)
{
    int kk = (it & 15) * 32;
    uint32_t base = sbase + (uint32_t)st * STAGE_BYTES;
#pragma unroll
    for (int j = 0; j < 4; j++) {          // A: 256 rows x 4 chunks
        int ch = tid + j * 256, r = ch >> 2, c = ch & 3;
        cpasync16(base + swoff(r, c),
                  A + (size_t)(rowBase + r) * ldA + kk + c * 8);
    }
#pragma unroll
    for (int j = 0; j < 2; j++) {          // B: 128 rows x 4 chunks
        int ch = tid + j * 256, r = ch >> 2, c = ch & 3;
        cpasync16(base + 16384 + swoff(r, c),
                  B + (size_t)(colBase + r) * ldB + kk + c * 8);
    }
    asm volatile("cp.async.commit_group;" ::: "memory");
}

// ---------------- 256x128 4-stage-pipelined tensor-core GEMM ----------------
// EPI: 1 = approx argmin + candidate append, 2 = fused CE partials,
//      3 = store bf16 C, 0 = store fp32 C.
template<int EPI, bool USE_HALF>
__global__ void __launch_bounds__(256) tcg256_kernel(
    const uint16_t* __restrict__ A, int ldA,
    const uint16_t* __restrict__ B, int ldB,
    float* __restrict__ C, int ldc)
{
    extern __shared__ __align__(16) unsigned char smem_s[];   // 4 x 24KB
    const int tid = threadIdx.x, lane = tid & 31, wid = tid >> 5;
    const int warp_m = wid & 3, warp_n = wid >> 2;   // 4m x 2n warps
    const int rowBase = blockIdx.y * 256;
    const int colBase = blockIdx.x * 128;
    const uint32_t sbase = smem_addr_u32(smem_s);

    float acc[4][8][4];
#pragma unroll
    for (int i = 0; i < 4; i++)
#pragma unroll
        for (int j = 0; j < 8; j++)
#pragma unroll
            for (int q = 0; q < 4; q++) acc[i][j][q] = 0.f;

    uint32_t offA[4][2], offB[4][2];
#pragma unroll
    for (int mt = 0; mt < 4; mt++) {
        int r = warp_m * 64 + mt * 16 + (lane & 15);
#pragma unroll
        for (int ks = 0; ks < 2; ks++)
            offA[mt][ks] = swoff(r, ks * 2 + (lane >> 4));
    }
#pragma unroll
    for (int p = 0; p < 4; p++) {
        int r = warp_n * 64 + p * 16 + (lane & 15);
#pragma unroll
        for (int ks = 0; ks < 2; ks++)
            offB[p][ks] = 16384u + swoff(r, ks * 2 + (lane >> 4));
    }

    const int nch = 16;   // K = 512
    tcg_load(A, ldA, B, ldB, rowBase, colBase, sbase, 0, 0, tid);
    tcg_load(A, ldA, B, ldB, rowBase, colBase, sbase, 1, 1, tid);
    tcg_load(A, ldA, B, ldB, rowBase, colBase, sbase, 2, 2, tid);

#pragma unroll 1
    for (int i = 0; i < nch; i++) {
        int rem = nch - 1 - i;
        if (rem >= 2)      asm volatile("cp.async.wait_group 2;" ::: "memory");
        else if (rem == 1) asm volatile("cp.async.wait_group 1;" ::: "memory");
        else               asm volatile("cp.async.wait_group 0;" ::: "memory");
        __syncthreads();
        if (i + 3 < nch)
            tcg_load(A, ldA, B, ldB, rowBase, colBase, sbase,
                     (i + 3) & 3, i + 3, tid);

        uint32_t stB = sbase + (uint32_t)(i & 3) * STAGE_BYTES;
#pragma unroll
        for (int ks = 0; ks < 2; ks++) {
            uint32_t af[4][4];
#pragma unroll
            for (int mt = 0; mt < 4; mt++) {
                uint32_t ad = stB + offA[mt][ks];
                asm volatile("ldmatrix.sync.aligned.m8n8.x4.shared.b16 {%0,%1,%2,%3}, [%4];"
                             : "=r"(af[mt][0]), "=r"(af[mt][1]),
                               "=r"(af[mt][2]), "=r"(af[mt][3]) : "r"(ad));
            }
            uint32_t bf[8][2];
#pragma unroll
            for (int p = 0; p < 4; p++) {
                uint32_t bd = stB + offB[p][ks];
                uint32_t q0, q1, q2, q3;
                asm volatile("ldmatrix.sync.aligned.m8n8.x4.shared.b16 {%0,%1,%2,%3}, [%4];"
                             : "=r"(q0), "=r"(q1), "=r"(q2), "=r"(q3) : "r"(bd));
                bf[2 * p][0] = q0; bf[2 * p][1] = q2;
                bf[2 * p + 1][0] = q1; bf[2 * p + 1][1] = q3;
            }
#pragma unroll
            for (int mt = 0; mt < 4; mt++)
#pragma unroll
                for (int nt = 0; nt < 8; nt++)
                    mma16816t<USE_HALF>(acc[mt][nt], af[mt], bf[nt]);
        }
    }

    if (EPI == 1) {
        // acc = 65536 * (x0 . e0); d_approx = fl(fl(esq+xsq) - 2*acc/65536).
        // Append every col within W of the 64-col group min (safe superset).
        const float INV = 1.0f / 65536.0f;
        const float e0m = __uint_as_float(g_en0max);
        const float e1m = __uint_as_float(g_en1max);
        const int rq = lane >> 2;
#pragma unroll
        for (int mt = 0; mt < 4; mt++) {
#pragma unroll
            for (int half = 0; half < 2; half++) {
                int row = rowBase + warp_m * 64 + mt * 16 + rq + half * 8;
                float xs = g_xsq[row];
                float W = 4.0f * INV * (g_xn0[row] * e1m +
                                        g_xn1[row] * (e0m + e1m)) + 1.3e-4f;
                float dd[16];
                float dmin = __int_as_float(0x7f800000);
#pragma unroll
                for (int nt = 0; nt < 8; nt++) {
#pragma unroll
                    for (int q = 0; q < 2; q++) {
                        int col = colBase + warp_n * 64 + nt * 8 + (lane & 3) * 2 + q;
                        float a = acc[mt][nt][half * 2 + q] * INV;
                        float t1 = __fadd_rn(g_esq[col], xs);
                        float d  = __fadd_rn(t1, -2.0f * a);
                        dd[nt * 2 + q] = d;
                        dmin = fminf(dmin, d);
                    }
                }
                dmin = fminf(dmin, __shfl_xor_sync(0xffffffffu, dmin, 1));
                dmin = fminf(dmin, __shfl_xor_sync(0xffffffffu, dmin, 2));
                if ((lane & 3) == 0) atomicMin(&g_dmin[row], fkey(dmin));
                float lim = dmin + W;
#pragma unroll
                for (int nt = 0; nt < 8; nt++) {
#pragma unroll
                    for (int q = 0; q < 2; q++) {
                        if (dd[nt * 2 + q] <= lim) {
                            int col = colBase + warp_n * 64 + nt * 8 + (lane & 3) * 2 + q;
                            int p = atomicAdd(&g_ncand, 1);
                            if (p < CAND_MAX) {
                                g_cand[p] = ((unsigned)row << 10) | (unsigned)col;
                                g_cdist[p] = dd[nt * 2 + q];
                            }
                        }
                    }
                }
            }
        }
    } else if (EPI == 2) {
        const int rq = lane >> 2;
#pragma unroll
        for (int mt = 0; mt < 4; mt++) {
#pragma unroll
            for (int half = 0; half < 2; half++) {
                int row = rowBase + warp_m * 64 + mt * 16 + rq + half * 8;
                int lab = g_labi[row];
                float mx = __int_as_float(0xff800000);
#pragma unroll
                for (int nt = 0; nt < 8; nt++)
#pragma unroll
                    for (int q = 0; q < 2; q++)
                        mx = fmaxf(mx, acc[mt][nt][half * 2 + q]);
                mx = fmaxf(mx, __shfl_xor_sync(0xffffffffu, mx, 1));
                mx = fmaxf(mx, __shfl_xor_sync(0xffffffffu, mx, 2));
                float s = 0.f;
#pragma unroll
                for (int nt = 0; nt < 8; nt++) {
#pragma unroll
                    for (int q = 0; q < 2; q++) {
                        float v = acc[mt][nt][half * 2 + q];
                        s += __expf(v - mx);
                        int col = colBase + warp_n * 64 + nt * 8 + (lane & 3) * 2 + q;
                        if (col == lab) g_labv[row] = v;
                    }
                }
                s += __shfl_xor_sync(0xffffffffu, s, 1);
                s += __shfl_xor_sync(0xffffffffu, s, 2);
                if ((lane & 3) == 0) {
                    int slab = blockIdx.x * 2 + warp_n;
                    g_pmax[(size_t)row * 16 + slab] = mx;
                    g_psum[(size_t)row * 16 + slab] = s;
                }
            }
        }
    } else if (EPI == 3) {
        __nv_bfloat16* Cb = (__nv_bfloat16*)C;
#pragma unroll
        for (int mt = 0; mt < 4; mt++) {
#pragma unroll
            for (int nt = 0; nt < 8; nt++) {
                int row0 = rowBase + warp_m * 64 + mt * 16 + (lane >> 2);
                int col  = colBase + warp_n * 64 + nt * 8 + (lane & 3) * 2;
                __nv_bfloat162 v0, v1;
                v0.x = __float2bfloat16(acc[mt][nt][0]);
                v0.y = __float2bfloat16(acc[mt][nt][1]);
                v1.x = __float2bfloat16(acc[mt][nt][2]);
                v1.y = __float2bfloat16(acc[mt][nt][3]);
                *(__nv_bfloat162*)(Cb + (size_t)row0 * ldc + col) = v0;
                *(__nv_bfloat162*)(Cb + (size_t)(row0 + 8) * ldc + col) = v1;
            }
        }
    } else {
#pragma unroll
        for (int mt = 0; mt < 4; mt++) {
#pragma unroll
            for (int nt = 0; nt < 8; nt++) {
                int row0 = rowBase + warp_m * 64 + mt * 16 + (lane >> 2);
                int col  = colBase + warp_n * 64 + nt * 8 + (lane & 3) * 2;
                *(float2*)(C + (size_t)row0 * ldc + col) =
                    make_float2(acc[mt][nt][0], acc[mt][nt][1]);
                *(float2*)(C + (size_t)(row0 + 8) * ldc + col) =
                    make_float2(acc[mt][nt][2], acc[mt][nt][3]);
            }
        }
    }
}

// ---------------- candidate filter + exact repass ----------------------------
__global__ void filter_kernel() {
    const float INV = 1.0f / 65536.0f;
    const float e0m = __uint_as_float(g_en0max);
    const float e1m = __uint_as_float(g_en1max);
    int n = min(g_ncand, CAND_MAX);
    for (int i = blockIdx.x * 256 + threadIdx.x; i < n; i += gridDim.x * 256) {
        unsigned pc = g_cand[i];
        int row = pc >> 10;
        float dm = inv_fkey(g_dmin[row]);
        float W = 4.0f * INV * (g_xn0[row] * e1m +
                                g_xn1[row] * (e0m + e1m)) + 1.3e-4f;
        if (g_cdist[i] <= dm + W) {
            int p = atomicAdd(&g_nsurv, 1);
            if (p < SURV_MAX) g_surv[p] = pc;
        }
    }
}

// exact fp32 distance for survivors; bucket-rounded argmin w/ low-index ties
__global__ void exact_kernel(const float* __restrict__ x,
                             const float* __restrict__ emb)
{
    int lane = threadIdx.x & 31;
    int wglob = (blockIdx.x * 256 + threadIdx.x) >> 5;
    int nwarp = (gridDim.x * 256) >> 5;
    int n = min(g_nsurv, SURV_MAX);
    for (int j = wglob; j < n; j += nwarp) {
        unsigned pc = g_surv[j];
        int row = pc >> 10, col = pc & 1023;
        const float* xr = x + (size_t)row * DDIM;
        const float* er = emb + (size_t)col * DDIM;
        float s = 0.f;
#pragma unroll 4
        for (int k = lane; k < DDIM; k += 32)
            s = fmaf(xr[k], er[k], s);
#pragma unroll
        for (int o = 16; o > 0; o >>= 1) s += __shfl_down_sync(0xffffffffu, s, o);
        if (lane == 0) {
            float t1 = __fadd_rn(g_esq[col], g_xsq[row]);
            float d  = __fadd_rn(t1, -2.0f * s);
            unsigned long long key =
                ((unsigned long long)fkey(d) << 32) | (unsigned)col;
            atomicMin(&g_best2[row], key);
        }
    }
}

// ---------------- weight transpose + bf16 convert ---------------------------
__global__ void wconv_kernel(const float* __restrict__ W,
                             __nv_bfloat16* __restrict__ Wt, int N)
{
    __shared__ float tile[32][33];
    int k0 = blockIdx.y * 32, n0 = blockIdx.x * 32;
    int tx = threadIdx.x & 31, ty = threadIdx.x >> 5;
#pragma unroll
    for (int i = 0; i < 32; i += 8)
        tile[ty + i][tx] = W[(size_t)(k0 + ty + i) * N + n0 + tx];
    __syncthreads();
#pragma unroll
    for (int i = 0; i < 32; i += 8)
        Wt[(size_t)(n0 + ty + i) * 512 + k0 + tx] = __float2bfloat16(tile[tx][ty + i]);
}

// ---------------- VQ bookkeeping: count / scan / scatter / dw-sum -----------
__global__ void countk_kernel() {
    int row = blockIdx.x * 256 + threadIdx.x;
    int idx = (int)(unsigned)(g_best2[row] & 0xFFFFFFFFull);
    atomicAdd(&g_cnti[idx], 1);
}

__global__ void prefix_kernel() {
    __shared__ int sh[MCODES];
    int t = threadIdx.x;
    int c = g_cnti[t];
    sh[t] = c;
    __syncthreads();
    for (int off = 1; off < MCODES; off <<= 1) {
        int add = (t >= off) ? sh[t - off] : 0;
        __syncthreads();
        sh[t] += add;
        __syncthreads();
    }
    g_off[t] = sh[t] - c;
    g_counts[t] = (float)c;
}

__global__ void scatter_kernel() {
    int row = blockIdx.x * 256 + threadIdx.x;
    int idx = (int)(unsigned)(g_best2[row] & 0xFFFFFFFFull);
    int p = atomicAdd(&g_fill[idx], 1);
    g_rows[g_off[idx] + p] = row;
}

// one block per code: sum assigned x rows, emit new_weight & new_embedding.
// out_emb/out_w are +1-float offset in packed output (4B aligned) -> scalar stores.
__global__ void dwsum_kernel(const float* __restrict__ x,
                             const float* __restrict__ ema_wt,
                             float* __restrict__ out_emb,
                             float* __restrict__ out_w)
{
    int m = blockIdx.x, t = threadIdx.x;
    int beg = g_off[m], cnt = g_cnti[m];
    float4 a0 = make_float4(0.f, 0.f, 0.f, 0.f);
    float4 a1 = make_float4(0.f, 0.f, 0.f, 0.f);
    int j = 0;
    for (; j + 1 < cnt; j += 2) {
        int r0 = g_rows[beg + j], r1 = g_rows[beg + j + 1];
        float4 v0 = ((const float4*)(x + (size_t)r0 * DDIM))[t];
        float4 v1 = ((const float4*)(x + (size_t)r1 * DDIM))[t];
        a0.x += v0.x; a0.y += v0.y; a0.z += v0.z; a0.w += v0.w;
        a1.x += v1.x; a1.y += v1.y; a1.z += v1.z; a1.w += v1.w;
    }
    if (j < cnt) {
        int r0 = g_rows[beg + j];
        float4 v0 = ((const float4*)(x + (size_t)r0 * DDIM))[t];
        a0.x += v0.x; a0.y += v0.y; a0.z += v0.z; a0.w += v0.w;
    }
    a0.x += a1.x; a0.y += a1.y; a0.z += a1.z; a0.w += a1.w;
    float4 w = ((const float4*)(ema_wt + (size_t)m * DDIM))[t];
    float nc = g_newc[m];
    float nw0 = 0.999f * w.x + 0.001f * a0.x;
    float nw1 = 0.999f * w.y + 0.001f * a0.y;
    float nw2 = 0.999f * w.z + 0.001f * a0.z;
    float nw3 = 0.999f * w.w + 0.001f * a0.w;
    size_t ob = (size_t)m * DDIM + t * 4;
    out_w[ob + 0] = nw0;
    out_w[ob + 1] = nw1;
    out_w[ob + 2] = nw2;
    out_w[ob + 3] = nw3;
    out_emb[ob + 0] = nw0 / nc;
    out_emb[ob + 1] = nw1 / nc;
    out_emb[ob + 2] = nw2 / nc;
    out_emb[ob + 3] = nw3 / nc;
}

// ---------------- post-VQ: gather, quantized_st, vq loss ---------------------
__global__ void postvq_kernel(const float* __restrict__ x,
                              const float* __restrict__ emb,
                              float* __restrict__ out_q)
{
    int row = blockIdx.x;
    int idx = (int)(unsigned)(g_best2[row] & 0xFFFFFFFFull);
    const float4* xr = (const float4*)(x   + (size_t)row * DDIM);
    const float4* er = (const float4*)(emb + (size_t)idx * DDIM);
    float4 xv = xr[threadIdx.x];
    float4 ev = er[threadIdx.x];
    float4 q;
    q.x = xv.x + (ev.x - xv.x);
    q.y = xv.y + (ev.y - xv.y);
    q.z = xv.z + (ev.z - xv.z);
    q.w = xv.w + (ev.w - xv.w);
    ((float4*)(out_q + (size_t)row * DDIM))[threadIdx.x] = q;

    float dx = xv.x - ev.x, dy = xv.y - ev.y, dz = xv.z - ev.z, dw2 = xv.w - ev.w;
    float s = dx * dx + dy * dy + dz * dz + dw2 * dw2;
    s = blockReduceSum(s);
    if (threadIdx.x == 0) g_vqrow[row] = 0.25f * s;
}

// ---------------- EMA count + perplexity ------------------------------------
__global__ void ema_kernel(const float* __restrict__ ema_count,
                           float* __restrict__ out_cnt,
                           float* __restrict__ out_perp)
{
    int m = threadIdx.x;
    float c = g_counts[m];
    float nc0 = 0.999f * ema_count[m] + 0.001f * c;
    float n = blockReduceSum(nc0);
    float newc = (nc0 + 1e-5f) / (n + (float)MCODES * 1e-5f) * n;
    out_cnt[m] = newc;
    g_newc[m] = newc;
    float p = c * (1.0f / (float)NROWS);
    float t = p * logf(p + 1e-10f);
    float s = blockReduceSum(t);
    if (m == 0) out_perp[0] = expf(-s);
}

// ---------------- LayerNorm + ReLU -> bf16 (templated input) ----------------
template<typename T>
__global__ void ln_relu_kernel(const T* __restrict__ X,
                               const float* __restrict__ g,
                               const float* __restrict__ b,
                               __nv_bfloat16* __restrict__ Y)
{
    constexpr int W = 512;
    constexpr int PER = 2;
    int row = blockIdx.x;
    const T* x = X + (size_t)row * W;
    float v[PER];
    float s = 0.f;
#pragma unroll
    for (int i = 0; i < PER; i++) { v[i] = (float)x[threadIdx.x + i * 256]; s += v[i]; }
    float mean = blockReduceSum(s) * (1.0f / W);
    float s2 = 0.f;
#pragma unroll
    for (int i = 0; i < PER; i++) { float d = v[i] - mean; s2 += d * d; }
    float var = blockReduceSum(s2) * (1.0f / W);
    float rstd = rsqrtf(var + 1e-5f);
#pragma unroll
    for (int i = 0; i < PER; i++) {
        int c = threadIdx.x + i * 256;
        float o = (v[i] - mean) * rstd * g[c] + b[c];
        Y[(size_t)row * W + c] = __float2bfloat16(fmaxf(o, 0.f));
    }
}

// ---------------- dtype detection + label convert ---------------------------
__global__ void detect_mask_kernel(const unsigned* __restrict__ m) {
    __shared__ int bad, gt1;
    if (threadIdx.x == 0) { bad = 0; gt1 = 0; }
    __syncthreads();
    for (int i = threadIdx.x; i < 8192; i += blockDim.x) {
        unsigned v = m[i];
        if (v > 1u) {
            atomicOr(&gt1, 1);
            if (v != 0x3F800000u) atomicOr(&bad, 1);
        }
    }
    __syncthreads();
    if (threadIdx.x == 0) g_mask_mode = (gt1 == 0) ? 0 : (bad ? 2 : 1);
}

__global__ void detect_lab_kernel(const unsigned* __restrict__ lab) {
    __shared__ int any_nz;
    if (threadIdx.x == 0) any_nz = 0;
    __syncthreads();
    for (int i = threadIdx.x; i < NROWS / 2; i += blockDim.x) {
        if (lab[2 * i + 1] != 0u) atomicOr(&any_nz, 1);
    }
    __syncthreads();
    if (threadIdx.x == 0) g_lab_mode = any_nz ? 0 : 1;
}

__global__ void labconv_kernel(const void* __restrict__ labels) {
    int i = blockIdx.x * 256 + threadIdx.x;
    g_labi[i] = g_lab_mode ? (int)((const long long*)labels)[i]
                           : ((const int*)labels)[i];
}

// ---------------- CE combine + final loss ------------------------------------
__global__ void ce_combine_kernel(const void* __restrict__ mask,
                                  float* __restrict__ out_loss)
{
    int row = blockIdx.x * 256 + threadIdx.x;
    const float* pm = g_pmax + (size_t)row * 16;
    const float* ps = g_psum + (size_t)row * 16;
    float M = __int_as_float(0xff800000);
#pragma unroll
    for (int i = 0; i < 16; i++) M = fmaxf(M, pm[i]);
    float S = 0.f;
#pragma unroll
    for (int i = 0; i < 16; i++) S += ps[i] * expf(pm[i] - M);
    float lse = M + logf(S);
    int mode = g_mask_mode;
    bool invalid;
    if (mode == 2)      invalid = ((const unsigned char*)mask)[row] != 0;
    else if (mode == 1) invalid = ((const float*)mask)[row] != 0.f;
    else                invalid = ((const int*)mask)[row] != 0;
    float ce = invalid ? 0.f : (lse - g_labv[row]);
    out_loss[row] = ce + g_vqrow[row];
}

// ---------------- launch -----------------------------------------------------
extern "C" void kernel_launch(void* const* d_in, const int* in_sizes, int n_in,
                              void* d_out, int out_size)
{
    const float* x         = (const float*)d_in[0];
    const void*  mask      = d_in[1];
    const void*  labels    = d_in[2];
    const float* emb       = (const float*)d_in[3];
    const float* ema_count = (const float*)d_in[4];
    const float* ema_wt    = (const float*)d_in[5];
    const float* ln1g      = (const float*)d_in[6];
    const float* ln1b      = (const float*)d_in[7];
    const float* W1        = (const float*)d_in[8];
    const float* ln2g      = (const float*)d_in[9];
    const float* ln2b      = (const float*)d_in[10];
    const float* W2        = (const float*)d_in[11];

    float* out      = (float*)d_out;
    float* out_q    = out;
    float* out_loss = out + (size_t)NROWS * DDIM;
    float* out_perp = out_loss + NROWS;
    float* out_emb  = out_perp + 1;
    float* out_cnt  = out_emb + (size_t)MCODES * DDIM;
    float* out_w    = out_cnt + MCODES;

    void *pa1, *phb, *pa2, *pxsq, *pesq, *pw1t, *pw2t, *pxs, *pes;
    void *pxn0, *pxn1, *pen0, *pen1, *pd0, *pd1, *pe0m, *pe1m;
    cudaGetSymbolAddress(&pa1, g_a1b);
    cudaGetSymbolAddress(&phb, g_hb);
    cudaGetSymbolAddress(&pa2, g_a2b);
    cudaGetSymbolAddress(&pxsq, g_xsq);
    cudaGetSymbolAddress(&pesq, g_esq);
    cudaGetSymbolAddress(&pw1t, g_w1t);
    cudaGetSymbolAddress(&pw2t, g_w2t);
    cudaGetSymbolAddress(&pxs, g_xs);
    cudaGetSymbolAddress(&pes, g_es);
    cudaGetSymbolAddress(&pxn0, g_xn0);
    cudaGetSymbolAddress(&pxn1, g_xn1);
    cudaGetSymbolAddress(&pen0, g_en0);
    cudaGetSymbolAddress(&pen1, g_en1);
    cudaGetSymbolAddress(&pd0, g_dummy0);
    cudaGetSymbolAddress(&pd1, g_dummy1);
    cudaGetSymbolAddress(&pe0m, g_en0max);
    cudaGetSymbolAddress(&pe1m, g_en1max);

    const int SMEM = 4 * 24576;   // 96 KB dynamic
    cudaFuncSetAttribute(tcg256_kernel<1, true>,
                         cudaFuncAttributeMaxDynamicSharedMemorySize, SMEM);
    cudaFuncSetAttribute(tcg256_kernel<3, false>,
                         cudaFuncAttributeMaxDynamicSharedMemorySize, SMEM);
    cudaFuncSetAttribute(tcg256_kernel<2, false>,
                         cudaFuncAttributeMaxDynamicSharedMemorySize, SMEM);

    // --- VQ path: main-term fp16 argmin + guaranteed candidate repair ---
    init_kernel<<<128, 256>>>();
    seqsq_kernel<<<MCODES, 128>>>(emb, (float*)pesq);
    seqsq_kernel<<<NROWS, 128>>>(x, (float*)pxsq);
    split2_kernel<<<NROWS / 2, 256>>>((const float4*)x, (__half*)pxs, 16.0f);
    split2_kernel<<<MCODES / 2, 256>>>((const float4*)emb, (__half*)pes, 4096.0f);
    norm2_kernel<<<NROWS, 256>>>((const __half*)pxs, (float*)pxn0, (float*)pxn1,
                                 (unsigned*)pd0, (unsigned*)pd1);
    norm2_kernel<<<MCODES, 256>>>((const __half*)pes, (float*)pen0, (float*)pen1,
                                  (unsigned*)pe0m, (unsigned*)pe1m);
    tcg256_kernel<1, true><<<dim3(MCODES / 128, NROWS / 256), 256, SMEM>>>(
        (const uint16_t*)pxs, 1024, (const uint16_t*)pes, 1024, nullptr, 0);
    filter_kernel<<<256, 256>>>();
    exact_kernel<<<1024, 256>>>(x, emb);

    // --- VQ bookkeeping: counts -> scan -> ema -> scatter -> dw/emb ---
    countk_kernel<<<NROWS / 256, 256>>>();
    prefix_kernel<<<1, MCODES>>>();
    ema_kernel<<<1, MCODES>>>(ema_count, out_cnt, out_perp);
    scatter_kernel<<<NROWS / 256, 256>>>();
    dwsum_kernel<<<MCODES, 128>>>(x, ema_wt, out_emb, out_w);
    postvq_kernel<<<NROWS, 128>>>(x, emb, out_q);

    // --- decoder path: bf16 tensor-core GEMMs (4-stage pipeline) ---
    wconv_kernel<<<dim3(HDIM / 32, DDIM / 32), 256>>>(W1, (__nv_bfloat16*)pw1t, HDIM);
    wconv_kernel<<<dim3(MCODES / 32, HDIM / 32), 256>>>(W2, (__nv_bfloat16*)pw2t, MCODES);
    ln_relu_kernel<float><<<NROWS, 256>>>(x, ln1g, ln1b, (__nv_bfloat16*)pa1);
    tcg256_kernel<3, false><<<dim3(HDIM / 128, NROWS / 256), 256, SMEM>>>(
        (const uint16_t*)pa1, 512, (const uint16_t*)pw1t, 512, (float*)phb, HDIM);
    ln_relu_kernel<__nv_bfloat16><<<NROWS, 256>>>((const __nv_bfloat16*)phb,
                                                  ln2g, ln2b, (__nv_bfloat16*)pa2);

    // --- W2 GEMM with fused CE partials, then combine ---
    detect_mask_kernel<<<1, 256>>>((const unsigned*)mask);
    detect_lab_kernel<<<1, 256>>>((const unsigned*)labels);
    labconv_kernel<<<NROWS / 256, 256>>>(labels);
    tcg256_kernel<2, false><<<dim3(MCODES / 128, NROWS / 256), 256, SMEM>>>(
        (const uint16_t*)pa2, 512, (const uint16_t*)pw2t, 512, nullptr, 0);
    ce_combine_kernel<<<NROWS / 256, 256>>>(mask, out_loss);
}

// round 13
// speedup vs baseline: 1.2939x; 1.2939x over previous
#include <cuda_runtime.h>
#include <cuda_bf16.h>
#include <cuda_fp16.h>
#include <cstdint>

#define NROWS 32768   // B*T
#define DDIM  512
#define HDIM  512
#define MCODES 1024
#define CAND_MAX (1 << 22)
#define SURV_MAX (1 << 20)

// ---------------- scratch (static device allocations; no cudaMalloc) -------
__device__ unsigned g_dmin[NROWS];                 // fkey(min d_approx) per row
__device__ unsigned long long g_best2[NROWS];      // final (fkey(d), col)
__device__ float g_counts[MCODES];
__device__ float g_esq[MCODES];
__device__ float g_xsq[NROWS];
__device__ float g_vqrow[NROWS];
__device__ float g_newc[MCODES];
__device__ int   g_mask_mode;
__device__ int   g_lab_mode;
__device__ int   g_labi[NROWS];
__device__ int   g_cnti[MCODES];
__device__ int   g_off[MCODES];
__device__ int   g_fill[MCODES];
__device__ int   g_rows[NROWS];
__device__ float g_pmax[(size_t)NROWS * 16];
__device__ float g_psum[(size_t)NROWS * 16];
__device__ float g_labv[NROWS];
__device__ float g_xn0[NROWS], g_xn1[NROWS];       // norms of scaled splits
__device__ float g_en0[MCODES], g_en1[MCODES];
__device__ unsigned g_en0max, g_en1max, g_dummy0, g_dummy1;
__device__ int   g_ncand, g_nsurv;
__device__ unsigned g_cand[CAND_MAX];
__device__ float    g_cdist[CAND_MAX];
__device__ unsigned g_surv[SURV_MAX];
__device__ __align__(16) __half g_xs[(size_t)NROWS * 1024];    // 16*x split
__device__ __align__(16) __half g_es[(size_t)MCODES * 1024];   // 4096*e split
__device__ __align__(16) __nv_bfloat16 g_a1b[(size_t)NROWS * DDIM];
__device__ __align__(16) __nv_bfloat16 g_a2b[(size_t)NROWS * HDIM];
__device__ __align__(16) __nv_bfloat16 g_hb[(size_t)NROWS * HDIM];
__device__ __align__(16) __nv_bfloat16 g_w1t[(size_t)HDIM * DDIM];
__device__ __align__(16) __nv_bfloat16 g_w2t[(size_t)MCODES * HDIM];

// ---------------- reduction helpers ----------------------------------------
__device__ __forceinline__ float warpReduceSum(float v) {
#pragma unroll
    for (int o = 16; o > 0; o >>= 1) v += __shfl_down_sync(0xffffffffu, v, o);
    return v;
}
__device__ __forceinline__ float blockReduceSum(float v) {
    __shared__ float s[32];
    __syncthreads();
    v = warpReduceSum(v);
    int lane = threadIdx.x & 31, w = threadIdx.x >> 5;
    if (lane == 0) s[w] = v;
    __syncthreads();
    int nw = blockDim.x >> 5;
    float r = (threadIdx.x < nw) ? s[threadIdx.x] : 0.f;
    if (w == 0) { r = warpReduceSum(r); if (lane == 0) s[0] = r; }
    __syncthreads();
    return s[0];
}
__device__ __forceinline__ unsigned fkey(float f) {
    unsigned u = __float_as_uint(f);
    return (u & 0x80000000u) ? ~u : (u | 0x80000000u);
}
__device__ __forceinline__ float inv_fkey(unsigned u) {
    return __uint_as_float((u & 0x80000000u) ? (u ^ 0x80000000u) : ~u);
}
__device__ __forceinline__ uint32_t smem_addr_u32(const void* p) {
    return (uint32_t)__cvta_generic_to_shared(p);
}

// ---------------- init ------------------------------------------------------
__global__ void init_kernel() {
    int i = blockIdx.x * blockDim.x + threadIdx.x;   // grid covers 32768
    g_dmin[i] = 0xFFFFFFFFu;
    g_best2[i] = ~0ull;
    if (i < MCODES) { g_cnti[i] = 0; g_fill[i] = 0; }
    if (i == 0) {
        g_ncand = 0; g_nsurv = 0;
        g_en0max = 0; g_en1max = 0; g_dummy0 = 0; g_dummy1 = 0;
    }
}

// Strict sequential fp32 sum of squares per row (reference rounding order).
__global__ void seqsq_kernel(const float* __restrict__ X, float* __restrict__ out) {
    __shared__ float row[DDIM];
    const float4* src = (const float4*)(X + (size_t)blockIdx.x * DDIM);
    ((float4*)row)[threadIdx.x] = src[threadIdx.x];
    __syncthreads();
    if (threadIdx.x == 0) {
        float s = 0.f;
#pragma unroll 8
        for (int i = 0; i < DDIM; i++)
            s = __fadd_rn(s, __fmul_rn(row[i], row[i]));
        out[blockIdx.x] = s;
    }
}

// 2-way fp16 split of scale*v, vectorized: 4 elems per thread
__global__ void split2_kernel(const float4* __restrict__ V,
                              __half* __restrict__ S, float scale)
{
    int i = blockIdx.x * 256 + threadIdx.x;
    int row = i >> 7, c4 = i & 127;
    float4 v = V[i];
    struct __align__(8) H4 { __half h[4]; } h0, h1;
    float vv[4] = {v.x * scale, v.y * scale, v.z * scale, v.w * scale};
#pragma unroll
    for (int k = 0; k < 4; k++) {
        __half a = __float2half_rn(vv[k]);
        h0.h[k] = a;
        h1.h[k] = __float2half_rn(vv[k] - __half2float(a));
    }
    size_t base = (size_t)row * 1024 + c4 * 4;
    *(uint2*)(S + base)       = *(uint2*)&h0;
    *(uint2*)(S + base + 512) = *(uint2*)&h1;
}

// per-row L2 norms of the two split halves (scaled domain) + global maxes
__global__ void norm2_kernel(const __half* __restrict__ S,
                             float* __restrict__ n0, float* __restrict__ n1,
                             unsigned* __restrict__ mx0, unsigned* __restrict__ mx1)
{
    int row = blockIdx.x;
    const __half* p = S + (size_t)row * 1024;
    float s0 = 0.f, s1 = 0.f;
#pragma unroll
    for (int i = 0; i < 2; i++) {
        float a = __half2float(p[threadIdx.x + i * 256]);
        float b = __half2float(p[512 + threadIdx.x + i * 256]);
        s0 += a * a;
        s1 += b * b;
    }
    s0 = blockReduceSum(s0);
    s1 = blockReduceSum(s1);
    if (threadIdx.x == 0) {
        float v0 = sqrtf(s0), v1 = sqrtf(s1);
        n0[row] = v0;
        n1[row] = v1;
        atomicMax(mx0, __float_as_uint(v0));
        atomicMax(mx1, __float_as_uint(v1));
    }
}

// ---------------- mma / cp.async helpers ------------------------------------
template<bool USE_HALF>
__device__ __forceinline__ void mma16816t(float* d, const uint32_t* a,
                                          const uint32_t* b) {
    if (USE_HALF)
        asm volatile(
            "mma.sync.aligned.m16n8k16.row.col.f32.f16.f16.f32 "
            "{%0,%1,%2,%3}, {%4,%5,%6,%7}, {%8,%9}, {%0,%1,%2,%3};"
            : "+f"(d[0]), "+f"(d[1]), "+f"(d[2]), "+f"(d[3])
            : "r"(a[0]), "r"(a[1]), "r"(a[2]), "r"(a[3]), "r"(b[0]), "r"(b[1]));
    else
        asm volatile(
            "mma.sync.aligned.m16n8k16.row.col.f32.bf16.bf16.f32 "
            "{%0,%1,%2,%3}, {%4,%5,%6,%7}, {%8,%9}, {%0,%1,%2,%3};"
            : "+f"(d[0]), "+f"(d[1]), "+f"(d[2]), "+f"(d[3])
            : "r"(a[0]), "r"(a[1]), "r"(a[2]), "r"(a[3]), "r"(b[0]), "r"(b[1]));
}

__device__ __forceinline__ void cpasync16(uint32_t dst, const void* src) {
    asm volatile("cp.async.cg.shared.global [%0], [%1], 16;"
                 :: "r"(dst), "l"(src) : "memory");
}

__device__ __forceinline__ uint32_t swoff(int r, int c) {
    return ((uint32_t)(r >> 1) << 7) |
           ((uint32_t)((((r & 1) << 2) | c) ^ ((r >> 1) & 7)) << 4);
}

#define STAGE_BYTES 24576u

__device__ __forceinline__ void tcg_load(
    const uint16_t* A, int ldA, const uint16_t* B, int ldB,
    int rowBase, int colBase, uint32_t sbase, int st, int it, int tid)
{
    int kk = (it & 15) * 32;
    uint32_t base = sbase + (uint32_t)st * STAGE_BYTES;
#pragma unroll
    for (int j = 0; j < 4; j++) {          // A: 256 rows x 4 chunks
        int ch = tid + j * 256, r = ch >> 2, c = ch & 3;
        cpasync16(base + swoff(r, c),
                  A + (size_t)(rowBase + r) * ldA + kk + c * 8);
    }
#pragma unroll
    for (int j = 0; j < 2; j++) {          // B: 128 rows x 4 chunks
        int ch = tid + j * 256, r = ch >> 2, c = ch & 3;
        cpasync16(base + 16384 + swoff(r, c),
                  B + (size_t)(colBase + r) * ldB + kk + c * 8);
    }
    asm volatile("cp.async.commit_group;" ::: "memory");
}

// ---------------- 256x128 4-stage-pipelined tensor-core GEMM ----------------
// EPI: 1 = approx argmin + block-aggregated candidate append,
//      2 = fused CE partials, 3 = store bf16 C, 0 = store fp32 C.
template<int EPI, bool USE_HALF>
__global__ void __launch_bounds__(256) tcg256_kernel(
    const uint16_t* __restrict__ A, int ldA,
    const uint16_t* __restrict__ B, int ldB,
    float* __restrict__ C, int ldc)
{
    extern __shared__ __align__(16) unsigned char smem_s[];   // 4 x 24KB
    const int tid = threadIdx.x, lane = tid & 31, wid = tid >> 5;
    const int warp_m = wid & 3, warp_n = wid >> 2;   // 4m x 2n warps
    const int rowBase = blockIdx.y * 256;
    const int colBase = blockIdx.x * 128;
    const uint32_t sbase = smem_addr_u32(smem_s);

    float acc[4][8][4];
#pragma unroll
    for (int i = 0; i < 4; i++)
#pragma unroll
        for (int j = 0; j < 8; j++)
#pragma unroll
            for (int q = 0; q < 4; q++) acc[i][j][q] = 0.f;

    uint32_t offA[4][2], offB[4][2];
#pragma unroll
    for (int mt = 0; mt < 4; mt++) {
        int r = warp_m * 64 + mt * 16 + (lane & 15);
#pragma unroll
        for (int ks = 0; ks < 2; ks++)
            offA[mt][ks] = swoff(r, ks * 2 + (lane >> 4));
    }
#pragma unroll
    for (int p = 0; p < 4; p++) {
        int r = warp_n * 64 + p * 16 + (lane & 15);
#pragma unroll
        for (int ks = 0; ks < 2; ks++)
            offB[p][ks] = 16384u + swoff(r, ks * 2 + (lane >> 4));
    }

    const int nch = 16;   // K = 512
    tcg_load(A, ldA, B, ldB, rowBase, colBase, sbase, 0, 0, tid);
    tcg_load(A, ldA, B, ldB, rowBase, colBase, sbase, 1, 1, tid);
    tcg_load(A, ldA, B, ldB, rowBase, colBase, sbase, 2, 2, tid);

#pragma unroll 1
    for (int i = 0; i < nch; i++) {
        int rem = nch - 1 - i;
        if (rem >= 2)      asm volatile("cp.async.wait_group 2;" ::: "memory");
        else if (rem == 1) asm volatile("cp.async.wait_group 1;" ::: "memory");
        else               asm volatile("cp.async.wait_group 0;" ::: "memory");
        __syncthreads();
        if (i + 3 < nch)
            tcg_load(A, ldA, B, ldB, rowBase, colBase, sbase,
                     (i + 3) & 3, i + 3, tid);

        uint32_t stB = sbase + (uint32_t)(i & 3) * STAGE_BYTES;
#pragma unroll
        for (int ks = 0; ks < 2; ks++) {
            uint32_t af[4][4];
#pragma unroll
            for (int mt = 0; mt < 4; mt++) {
                uint32_t ad = stB + offA[mt][ks];
                asm volatile("ldmatrix.sync.aligned.m8n8.x4.shared.b16 {%0,%1,%2,%3}, [%4];"
                             : "=r"(af[mt][0]), "=r"(af[mt][1]),
                               "=r"(af[mt][2]), "=r"(af[mt][3]) : "r"(ad));
            }
            uint32_t bf[8][2];
#pragma unroll
            for (int p = 0; p < 4; p++) {
                uint32_t bd = stB + offB[p][ks];
                uint32_t q0, q1, q2, q3;
                asm volatile("ldmatrix.sync.aligned.m8n8.x4.shared.b16 {%0,%1,%2,%3}, [%4];"
                             : "=r"(q0), "=r"(q1), "=r"(q2), "=r"(q3) : "r"(bd));
                bf[2 * p][0] = q0; bf[2 * p][1] = q2;
                bf[2 * p + 1][0] = q1; bf[2 * p + 1][1] = q3;
            }
#pragma unroll
            for (int mt = 0; mt < 4; mt++)
#pragma unroll
                for (int nt = 0; nt < 8; nt++)
                    mma16816t<USE_HALF>(acc[mt][nt], af[mt], bf[nt]);
        }
    }

    if (EPI == 1) {
        // acc = 65536 * (x0 . e0); d_approx = fl(fl(esq+xsq) - 2*acc/65536).
        // Pass 1: group min + candidate count. Block scan. One atomicAdd/CTA.
        // Pass 2: write candidates at scanned offsets.
        const float INV = 1.0f / 65536.0f;
        const float e0m = __uint_as_float(g_en0max);
        const float e1m = __uint_as_float(g_en1max);
        const int rq = lane >> 2;
        float lims[8];
        int cnt = 0;
        __syncthreads();   // smem reuse safe (ldmatrix of last chunk done)
#pragma unroll
        for (int mt = 0; mt < 4; mt++) {
#pragma unroll
            for (int half = 0; half < 2; half++) {
                int row = rowBase + warp_m * 64 + mt * 16 + rq + half * 8;
                float xs = g_xsq[row];
                float W = 4.0f * INV * (g_xn0[row] * e1m +
                                        g_xn1[row] * (e0m + e1m)) + 1.3e-4f;
                float dmin = __int_as_float(0x7f800000);
                float dd[16];
#pragma unroll
                for (int nt = 0; nt < 8; nt++) {
#pragma unroll
                    for (int q = 0; q < 2; q++) {
                        int col = colBase + warp_n * 64 + nt * 8 + (lane & 3) * 2 + q;
                        float a = acc[mt][nt][half * 2 + q] * INV;
                        float t1 = __fadd_rn(g_esq[col], xs);
                        float d  = __fadd_rn(t1, -2.0f * a);
                        dd[nt * 2 + q] = d;
                        dmin = fminf(dmin, d);
                    }
                }
                dmin = fminf(dmin, __shfl_xor_sync(0xffffffffu, dmin, 1));
                dmin = fminf(dmin, __shfl_xor_sync(0xffffffffu, dmin, 2));
                if ((lane & 3) == 0) atomicMin(&g_dmin[row], fkey(dmin));
                float lim = dmin + W;
                lims[mt * 2 + half] = lim;
#pragma unroll
                for (int j = 0; j < 16; j++)
                    if (dd[j] <= lim) cnt++;
            }
        }
        // block scan of cnt (Hillis-Steele over 256 lanes in smem)
        int* sc = (int*)smem_s;
        sc[tid] = cnt;
        __syncthreads();
#pragma unroll
        for (int off = 1; off < 256; off <<= 1) {
            int add = (tid >= off) ? sc[tid - off] : 0;
            __syncthreads();
            sc[tid] += add;
            __syncthreads();
        }
        int* basep = sc + 256;
        if (tid == 255) *basep = atomicAdd(&g_ncand, sc[255]);
        __syncthreads();
        int mybase = *basep + sc[tid] - cnt;
        // pass 2: recompute + write
        int k = 0;
#pragma unroll
        for (int mt = 0; mt < 4; mt++) {
#pragma unroll
            for (int half = 0; half < 2; half++) {
                int row = rowBase + warp_m * 64 + mt * 16 + rq + half * 8;
                float xs = g_xsq[row];
                float lim = lims[mt * 2 + half];
#pragma unroll
                for (int nt = 0; nt < 8; nt++) {
#pragma unroll
                    for (int q = 0; q < 2; q++) {
                        int col = colBase + warp_n * 64 + nt * 8 + (lane & 3) * 2 + q;
                        float a = acc[mt][nt][half * 2 + q] * INV;
                        float t1 = __fadd_rn(g_esq[col], xs);
                        float d  = __fadd_rn(t1, -2.0f * a);
                        if (d <= lim) {
                            int p = mybase + k;
                            if (p < CAND_MAX) {
                                g_cand[p] = ((unsigned)row << 10) | (unsigned)col;
                                g_cdist[p] = d;
                            }
                            k++;
                        }
                    }
                }
            }
        }
    } else if (EPI == 2) {
        const int rq = lane >> 2;
#pragma unroll
        for (int mt = 0; mt < 4; mt++) {
#pragma unroll
            for (int half = 0; half < 2; half++) {
                int row = rowBase + warp_m * 64 + mt * 16 + rq + half * 8;
                int lab = g_labi[row];
                float mx = __int_as_float(0xff800000);
#pragma unroll
                for (int nt = 0; nt < 8; nt++)
#pragma unroll
                    for (int q = 0; q < 2; q++)
                        mx = fmaxf(mx, acc[mt][nt][half * 2 + q]);
                mx = fmaxf(mx, __shfl_xor_sync(0xffffffffu, mx, 1));
                mx = fmaxf(mx, __shfl_xor_sync(0xffffffffu, mx, 2));
                float s = 0.f;
#pragma unroll
                for (int nt = 0; nt < 8; nt++) {
#pragma unroll
                    for (int q = 0; q < 2; q++) {
                        float v = acc[mt][nt][half * 2 + q];
                        s += __expf(v - mx);
                        int col = colBase + warp_n * 64 + nt * 8 + (lane & 3) * 2 + q;
                        if (col == lab) g_labv[row] = v;
                    }
                }
                s += __shfl_xor_sync(0xffffffffu, s, 1);
                s += __shfl_xor_sync(0xffffffffu, s, 2);
                if ((lane & 3) == 0) {
                    int slab = blockIdx.x * 2 + warp_n;
                    g_pmax[(size_t)row * 16 + slab] = mx;
                    g_psum[(size_t)row * 16 + slab] = s;
                }
            }
        }
    } else if (EPI == 3) {
        __nv_bfloat16* Cb = (__nv_bfloat16*)C;
#pragma unroll
        for (int mt = 0; mt < 4; mt++) {
#pragma unroll
            for (int nt = 0; nt < 8; nt++) {
                int row0 = rowBase + warp_m * 64 + mt * 16 + (lane >> 2);
                int col  = colBase + warp_n * 64 + nt * 8 + (lane & 3) * 2;
                __nv_bfloat162 v0, v1;
                v0.x = __float2bfloat16(acc[mt][nt][0]);
                v0.y = __float2bfloat16(acc[mt][nt][1]);
                v1.x = __float2bfloat16(acc[mt][nt][2]);
                v1.y = __float2bfloat16(acc[mt][nt][3]);
                *(__nv_bfloat162*)(Cb + (size_t)row0 * ldc + col) = v0;
                *(__nv_bfloat162*)(Cb + (size_t)(row0 + 8) * ldc + col) = v1;
            }
        }
    } else {
#pragma unroll
        for (int mt = 0; mt < 4; mt++) {
#pragma unroll
            for (int nt = 0; nt < 8; nt++) {
                int row0 = rowBase + warp_m * 64 + mt * 16 + (lane >> 2);
                int col  = colBase + warp_n * 64 + nt * 8 + (lane & 3) * 2;
                *(float2*)(C + (size_t)row0 * ldc + col) =
                    make_float2(acc[mt][nt][0], acc[mt][nt][1]);
                *(float2*)(C + (size_t)(row0 + 8) * ldc + col) =
                    make_float2(acc[mt][nt][2], acc[mt][nt][3]);
            }
        }
    }
}

// ---------------- candidate filter + exact repass ----------------------------
__global__ void filter_kernel() {
    const float INV = 1.0f / 65536.0f;
    const float e0m = __uint_as_float(g_en0max);
    const float e1m = __uint_as_float(g_en1max);
    int n = min(g_ncand, CAND_MAX);
    for (int i = blockIdx.x * 256 + threadIdx.x; i < n; i += gridDim.x * 256) {
        unsigned pc = g_cand[i];
        int row = pc >> 10;
        float dm = inv_fkey(g_dmin[row]);
        float W = 4.0f * INV * (g_xn0[row] * e1m +
                                g_xn1[row] * (e0m + e1m)) + 1.3e-4f;
        if (g_cdist[i] <= dm + W) {
            int p = atomicAdd(&g_nsurv, 1);
            if (p < SURV_MAX) g_surv[p] = pc;
        }
    }
}

// exact fp32 distance for survivors; bucket-rounded argmin w/ low-index ties
__global__ void exact_kernel(const float* __restrict__ x,
                             const float* __restrict__ emb)
{
    int lane = threadIdx.x & 31;
    int wglob = (blockIdx.x * 256 + threadIdx.x) >> 5;
    int nwarp = (gridDim.x * 256) >> 5;
    int n = min(g_nsurv, SURV_MAX);
    for (int j = wglob; j < n; j += nwarp) {
        unsigned pc = g_surv[j];
        int row = pc >> 10, col = pc & 1023;
        const float* xr = x + (size_t)row * DDIM;
        const float* er = emb + (size_t)col * DDIM;
        float s = 0.f;
#pragma unroll 4
        for (int k = lane; k < DDIM; k += 32)
            s = fmaf(xr[k], er[k], s);
#pragma unroll
        for (int o = 16; o > 0; o >>= 1) s += __shfl_down_sync(0xffffffffu, s, o);
        if (lane == 0) {
            float t1 = __fadd_rn(g_esq[col], g_xsq[row]);
            float d  = __fadd_rn(t1, -2.0f * s);
            unsigned long long key =
                ((unsigned long long)fkey(d) << 32) | (unsigned)col;
            atomicMin(&g_best2[row], key);
        }
    }
}

// ---------------- weight transpose + bf16 convert ---------------------------
__global__ void wconv_kernel(const float* __restrict__ W,
                             __nv_bfloat16* __restrict__ Wt, int N)
{
    __shared__ float tile[32][33];
    int k0 = blockIdx.y * 32, n0 = blockIdx.x * 32;
    int tx = threadIdx.x & 31, ty = threadIdx.x >> 5;
#pragma unroll
    for (int i = 0; i < 32; i += 8)
        tile[ty + i][tx] = W[(size_t)(k0 + ty + i) * N + n0 + tx];
    __syncthreads();
#pragma unroll
    for (int i = 0; i < 32; i += 8)
        Wt[(size_t)(n0 + ty + i) * 512 + k0 + tx] = __float2bfloat16(tile[tx][ty + i]);
}

// ---------------- VQ bookkeeping: count / scan / scatter / dw-sum -----------
__global__ void countk_kernel() {
    int row = blockIdx.x * 256 + threadIdx.x;
    int idx = (int)(unsigned)(g_best2[row] & 0xFFFFFFFFull);
    atomicAdd(&g_cnti[idx], 1);
}

__global__ void prefix_kernel() {
    __shared__ int sh[MCODES];
    int t = threadIdx.x;
    int c = g_cnti[t];
    sh[t] = c;
    __syncthreads();
    for (int off = 1; off < MCODES; off <<= 1) {
        int add = (t >= off) ? sh[t - off] : 0;
        __syncthreads();
        sh[t] += add;
        __syncthreads();
    }
    g_off[t] = sh[t] - c;
    g_counts[t] = (float)c;
}

__global__ void scatter_kernel() {
    int row = blockIdx.x * 256 + threadIdx.x;
    int idx = (int)(unsigned)(g_best2[row] & 0xFFFFFFFFull);
    int p = atomicAdd(&g_fill[idx], 1);
    g_rows[g_off[idx] + p] = row;
}

// one block per code: sum assigned x rows, emit new_weight & new_embedding.
// out_emb/out_w are +1-float offset in packed output (4B aligned) -> scalar stores.
__global__ void dwsum_kernel(const float* __restrict__ x,
                             const float* __restrict__ ema_wt,
                             float* __restrict__ out_emb,
                             float* __restrict__ out_w)
{
    int m = blockIdx.x, t = threadIdx.x;
    int beg = g_off[m], cnt = g_cnti[m];
    float4 a0 = make_float4(0.f, 0.f, 0.f, 0.f);
    float4 a1 = make_float4(0.f, 0.f, 0.f, 0.f);
    int j = 0;
    for (; j + 1 < cnt; j += 2) {
        int r0 = g_rows[beg + j], r1 = g_rows[beg + j + 1];
        float4 v0 = ((const float4*)(x + (size_t)r0 * DDIM))[t];
        float4 v1 = ((const float4*)(x + (size_t)r1 * DDIM))[t];
        a0.x += v0.x; a0.y += v0.y; a0.z += v0.z; a0.w += v0.w;
        a1.x += v1.x; a1.y += v1.y; a1.z += v1.z; a1.w += v1.w;
    }
    if (j < cnt) {
        int r0 = g_rows[beg + j];
        float4 v0 = ((const float4*)(x + (size_t)r0 * DDIM))[t];
        a0.x += v0.x; a0.y += v0.y; a0.z += v0.z; a0.w += v0.w;
    }
    a0.x += a1.x; a0.y += a1.y; a0.z += a1.z; a0.w += a1.w;
    float4 w = ((const float4*)(ema_wt + (size_t)m * DDIM))[t];
    float nc = g_newc[m];
    float nw0 = 0.999f * w.x + 0.001f * a0.x;
    float nw1 = 0.999f * w.y + 0.001f * a0.y;
    float nw2 = 0.999f * w.z + 0.001f * a0.z;
    float nw3 = 0.999f * w.w + 0.001f * a0.w;
    size_t ob = (size_t)m * DDIM + t * 4;
    out_w[ob + 0] = nw0;
    out_w[ob + 1] = nw1;
    out_w[ob + 2] = nw2;
    out_w[ob + 3] = nw3;
    out_emb[ob + 0] = nw0 / nc;
    out_emb[ob + 1] = nw1 / nc;
    out_emb[ob + 2] = nw2 / nc;
    out_emb[ob + 3] = nw3 / nc;
}

// ---------------- post-VQ: gather, quantized_st, vq loss ---------------------
__global__ void postvq_kernel(const float* __restrict__ x,
                              const float* __restrict__ emb,
                              float* __restrict__ out_q)
{
    int row = blockIdx.x;
    int idx = (int)(unsigned)(g_best2[row] & 0xFFFFFFFFull);
    const float4* xr = (const float4*)(x   + (size_t)row * DDIM);
    const float4* er = (const float4*)(emb + (size_t)idx * DDIM);
    float4 xv = xr[threadIdx.x];
    float4 ev = er[threadIdx.x];
    float4 q;
    q.x = xv.x + (ev.x - xv.x);
    q.y = xv.y + (ev.y - xv.y);
    q.z = xv.z + (ev.z - xv.z);
    q.w = xv.w + (ev.w - xv.w);
    ((float4*)(out_q + (size_t)row * DDIM))[threadIdx.x] = q;

    float dx = xv.x - ev.x, dy = xv.y - ev.y, dz = xv.z - ev.z, dw2 = xv.w - ev.w;
    float s = dx * dx + dy * dy + dz * dz + dw2 * dw2;
    s = blockReduceSum(s);
    if (threadIdx.x == 0) g_vqrow[row] = 0.25f * s;
}

// ---------------- EMA count + perplexity ------------------------------------
__global__ void ema_kernel(const float* __restrict__ ema_count,
                           float* __restrict__ out_cnt,
                           float* __restrict__ out_perp)
{
    int m = threadIdx.x;
    float c = g_counts[m];
    float nc0 = 0.999f * ema_count[m] + 0.001f * c;
    float n = blockReduceSum(nc0);
    float newc = (nc0 + 1e-5f) / (n + (float)MCODES * 1e-5f) * n;
    out_cnt[m] = newc;
    g_newc[m] = newc;
    float p = c * (1.0f / (float)NROWS);
    float t = p * logf(p + 1e-10f);
    float s = blockReduceSum(t);
    if (m == 0) out_perp[0] = expf(-s);
}

// ---------------- LayerNorm + ReLU -> bf16 (templated input) ----------------
template<typename T>
__global__ void ln_relu_kernel(const T* __restrict__ X,
                               const float* __restrict__ g,
                               const float* __restrict__ b,
                               __nv_bfloat16* __restrict__ Y)
{
    constexpr int W = 512;
    constexpr int PER = 2;
    int row = blockIdx.x;
    const T* x = X + (size_t)row * W;
    float v[PER];
    float s = 0.f;
#pragma unroll
    for (int i = 0; i < PER; i++) { v[i] = (float)x[threadIdx.x + i * 256]; s += v[i]; }
    float mean = blockReduceSum(s) * (1.0f / W);
    float s2 = 0.f;
#pragma unroll
    for (int i = 0; i < PER; i++) { float d = v[i] - mean; s2 += d * d; }
    float var = blockReduceSum(s2) * (1.0f / W);
    float rstd = rsqrtf(var + 1e-5f);
#pragma unroll
    for (int i = 0; i < PER; i++) {
        int c = threadIdx.x + i * 256;
        float o = (v[i] - mean) * rstd * g[c] + b[c];
        Y[(size_t)row * W + c] = __float2bfloat16(fmaxf(o, 0.f));
    }
}

// ---------------- dtype detection + label convert ---------------------------
__global__ void detect_mask_kernel(const unsigned* __restrict__ m) {
    __shared__ int bad, gt1;
    if (threadIdx.x == 0) { bad = 0; gt1 = 0; }
    __syncthreads();
    for (int i = threadIdx.x; i < 8192; i += blockDim.x) {
        unsigned v = m[i];
        if (v > 1u) {
            atomicOr(&gt1, 1);
            if (v != 0x3F800000u) atomicOr(&bad, 1);
        }
    }
    __syncthreads();
    if (threadIdx.x == 0) g_mask_mode = (gt1 == 0) ? 0 : (bad ? 2 : 1);
}

__global__ void detect_lab_kernel(const unsigned* __restrict__ lab) {
    __shared__ int any_nz;
    if (threadIdx.x == 0) any_nz = 0;
    __syncthreads();
    for (int i = threadIdx.x; i < NROWS / 2; i += blockDim.x) {
        if (lab[2 * i + 1] != 0u) atomicOr(&any_nz, 1);
    }
    __syncthreads();
    if (threadIdx.x == 0) g_lab_mode = any_nz ? 0 : 1;
}

__global__ void labconv_kernel(const void* __restrict__ labels) {
    int i = blockIdx.x * 256 + threadIdx.x;
    g_labi[i] = g_lab_mode ? (int)((const long long*)labels)[i]
                           : ((const int*)labels)[i];
}

// ---------------- CE combine + final loss ------------------------------------
__global__ void ce_combine_kernel(const void* __restrict__ mask,
                                  float* __restrict__ out_loss)
{
    int row = blockIdx.x * 256 + threadIdx.x;
    const float* pm = g_pmax + (size_t)row * 16;
    const float* ps = g_psum + (size_t)row * 16;
    float M = __int_as_float(0xff800000);
#pragma unroll
    for (int i = 0; i < 16; i++) M = fmaxf(M, pm[i]);
    float S = 0.f;
#pragma unroll
    for (int i = 0; i < 16; i++) S += ps[i] * expf(pm[i] - M);
    float lse = M + logf(S);
    int mode = g_mask_mode;
    bool invalid;
    if (mode == 2)      invalid = ((const unsigned char*)mask)[row] != 0;
    else if (mode == 1) invalid = ((const float*)mask)[row] != 0.f;
    else                invalid = ((const int*)mask)[row] != 0;
    float ce = invalid ? 0.f : (lse - g_labv[row]);
    out_loss[row] = ce + g_vqrow[row];
}

// ---------------- launch -----------------------------------------------------
extern "C" void kernel_launch(void* const* d_in, const int* in_sizes, int n_in,
                              void* d_out, int out_size)
{
    const float* x         = (const float*)d_in[0];
    const void*  mask      = d_in[1];
    const void*  labels    = d_in[2];
    const float* emb       = (const float*)d_in[3];
    const float* ema_count = (const float*)d_in[4];
    const float* ema_wt    = (const float*)d_in[5];
    const float* ln1g      = (const float*)d_in[6];
    const float* ln1b      = (const float*)d_in[7];
    const float* W1        = (const float*)d_in[8];
    const float* ln2g      = (const float*)d_in[9];
    const float* ln2b      = (const float*)d_in[10];
    const float* W2        = (const float*)d_in[11];

    float* out      = (float*)d_out;
    float* out_q    = out;
    float* out_loss = out + (size_t)NROWS * DDIM;
    float* out_perp = out_loss + NROWS;
    float* out_emb  = out_perp + 1;
    float* out_cnt  = out_emb + (size_t)MCODES * DDIM;
    float* out_w    = out_cnt + MCODES;

    void *pa1, *phb, *pa2, *pxsq, *pesq, *pw1t, *pw2t, *pxs, *pes;
    void *pxn0, *pxn1, *pen0, *pen1, *pd0, *pd1, *pe0m, *pe1m;
    cudaGetSymbolAddress(&pa1, g_a1b);
    cudaGetSymbolAddress(&phb, g_hb);
    cudaGetSymbolAddress(&pa2, g_a2b);
    cudaGetSymbolAddress(&pxsq, g_xsq);
    cudaGetSymbolAddress(&pesq, g_esq);
    cudaGetSymbolAddress(&pw1t, g_w1t);
    cudaGetSymbolAddress(&pw2t, g_w2t);
    cudaGetSymbolAddress(&pxs, g_xs);
    cudaGetSymbolAddress(&pes, g_es);
    cudaGetSymbolAddress(&pxn0, g_xn0);
    cudaGetSymbolAddress(&pxn1, g_xn1);
    cudaGetSymbolAddress(&pen0, g_en0);
    cudaGetSymbolAddress(&pen1, g_en1);
    cudaGetSymbolAddress(&pd0, g_dummy0);
    cudaGetSymbolAddress(&pd1, g_dummy1);
    cudaGetSymbolAddress(&pe0m, g_en0max);
    cudaGetSymbolAddress(&pe1m, g_en1max);

    const int SMEM = 4 * 24576;   // 96 KB dynamic
    cudaFuncSetAttribute(tcg256_kernel<1, true>,
                         cudaFuncAttributeMaxDynamicSharedMemorySize, SMEM);
    cudaFuncSetAttribute(tcg256_kernel<3, false>,
                         cudaFuncAttributeMaxDynamicSharedMemorySize, SMEM);
    cudaFuncSetAttribute(tcg256_kernel<2, false>,
                         cudaFuncAttributeMaxDynamicSharedMemorySize, SMEM);

    // --- VQ path: main-term fp16 argmin + guaranteed candidate repair ---
    init_kernel<<<128, 256>>>();
    seqsq_kernel<<<MCODES, 128>>>(emb, (float*)pesq);
    seqsq_kernel<<<NROWS, 128>>>(x, (float*)pxsq);
    split2_kernel<<<NROWS / 2, 256>>>((const float4*)x, (__half*)pxs, 16.0f);
    split2_kernel<<<MCODES / 2, 256>>>((const float4*)emb, (__half*)pes, 4096.0f);
    norm2_kernel<<<NROWS, 256>>>((const __half*)pxs, (float*)pxn0, (float*)pxn1,
                                 (unsigned*)pd0, (unsigned*)pd1);
    norm2_kernel<<<MCODES, 256>>>((const __half*)pes, (float*)pen0, (float*)pen1,
                                  (unsigned*)pe0m, (unsigned*)pe1m);
    tcg256_kernel<1, true><<<dim3(MCODES / 128, NROWS / 256), 256, SMEM>>>(
        (const uint16_t*)pxs, 1024, (const uint16_t*)pes, 1024, nullptr, 0);
    filter_kernel<<<256, 256>>>();
    exact_kernel<<<1024, 256>>>(x, emb);

    // --- VQ bookkeeping: counts -> scan -> ema -> scatter -> dw/emb ---
    countk_kernel<<<NROWS / 256, 256>>>();
    prefix_kernel<<<1, MCODES>>>();
    ema_kernel<<<1, MCODES>>>(ema_count, out_cnt, out_perp);
    scatter_kernel<<<NROWS / 256, 256>>>();
    dwsum_kernel<<<MCODES, 128>>>(x, ema_wt, out_emb, out_w);
    postvq_kernel<<<NROWS, 128>>>(x, emb, out_q);

    // --- decoder path: bf16 tensor-core GEMMs (4-stage pipeline) ---
    wconv_kernel<<<dim3(HDIM / 32, DDIM / 32), 256>>>(W1, (__nv_bfloat16*)pw1t, HDIM);
    wconv_kernel<<<dim3(MCODES / 32, HDIM / 32), 256>>>(W2, (__nv_bfloat16*)pw2t, MCODES);
    ln_relu_kernel<float><<<NROWS, 256>>>(x, ln1g, ln1b, (__nv_bfloat16*)pa1);
    tcg256_kernel<3, false><<<dim3(HDIM / 128, NROWS / 256), 256, SMEM>>>(
        (const uint16_t*)pa1, 512, (const uint16_t*)pw1t, 512, (float*)phb, HDIM);
    ln_relu_kernel<__nv_bfloat16><<<NROWS, 256>>>((const __nv_bfloat16*)phb,
                                                  ln2g, ln2b, (__nv_bfloat16*)pa2);

    // --- W2 GEMM with fused CE partials, then combine ---
    detect_mask_kernel<<<1, 256>>>((const unsigned*)mask);
    detect_lab_kernel<<<1, 256>>>((const unsigned*)labels);
    labconv_kernel<<<NROWS / 256, 256>>>(labels);
    tcg256_kernel<2, false><<<dim3(MCODES / 128, NROWS / 256), 256, SMEM>>>(
        (const uint16_t*)pa2, 512, (const uint16_t*)pw2t, 512, nullptr, 0);
    ce_combine_kernel<<<NROWS / 256, 256>>>(mask, out_loss);
}

// round 14
// speedup vs baseline: 1.4712x; 1.1370x over previous
#include <cuda_runtime.h>
#include <cuda_bf16.h>
#include <cuda_fp16.h>
#include <cstdint>

#define NROWS 32768   // B*T
#define DDIM  512
#define HDIM  512
#define MCODES 1024
#define CAND_MAX (1 << 22)
#define SURV_MAX (1 << 20)

// ---------------- scratch (static device allocations; no cudaMalloc) -------
__device__ unsigned g_dmin[NROWS];                 // fkey(min d_approx) per row
__device__ unsigned long long g_best2[NROWS];      // final (fkey(d), col)
__device__ float g_counts[MCODES];
__device__ float g_esq[MCODES];
__device__ float g_xsq[NROWS];
__device__ float g_vqrow[NROWS];
__device__ float g_newc[MCODES];
__device__ int   g_mask_mode;
__device__ int   g_lab_mode;
__device__ int   g_labi[NROWS];
__device__ int   g_cnti[MCODES];
__device__ int   g_off[MCODES];
__device__ int   g_fill[MCODES];
__device__ int   g_rows[NROWS];
__device__ float g_pmax[(size_t)NROWS * 16];
__device__ float g_psum[(size_t)NROWS * 16];
__device__ float g_labv[NROWS];
__device__ float g_xn0[NROWS], g_xn1[NROWS];       // norms of scaled splits
__device__ float g_en0[MCODES], g_en1[MCODES];
__device__ unsigned g_en0max, g_en1max, g_dummy0, g_dummy1;
__device__ int   g_ncand, g_nsurv;
__device__ unsigned g_cand[CAND_MAX];
__device__ float    g_cdist[CAND_MAX];
__device__ unsigned g_surv[SURV_MAX];
__device__ __align__(16) __half g_xs[(size_t)NROWS * 1024];    // 16*x split
__device__ __align__(16) __half g_es[(size_t)MCODES * 1024];   // 4096*e split
__device__ __align__(16) __nv_bfloat16 g_a1b[(size_t)NROWS * DDIM];
__device__ __align__(16) __nv_bfloat16 g_a2b[(size_t)NROWS * HDIM];
__device__ __align__(16) __nv_bfloat16 g_hb[(size_t)NROWS * HDIM];
__device__ __align__(16) __nv_bfloat16 g_w1t[(size_t)HDIM * DDIM];
__device__ __align__(16) __nv_bfloat16 g_w2t[(size_t)MCODES * HDIM];

// ---------------- reduction helpers ----------------------------------------
__device__ __forceinline__ float warpReduceSum(float v) {
#pragma unroll
    for (int o = 16; o > 0; o >>= 1) v += __shfl_down_sync(0xffffffffu, v, o);
    return v;
}
__device__ __forceinline__ float blockReduceSum(float v) {
    __shared__ float s[32];
    __syncthreads();
    v = warpReduceSum(v);
    int lane = threadIdx.x & 31, w = threadIdx.x >> 5;
    if (lane == 0) s[w] = v;
    __syncthreads();
    int nw = blockDim.x >> 5;
    float r = (threadIdx.x < nw) ? s[threadIdx.x] : 0.f;
    if (w == 0) { r = warpReduceSum(r); if (lane == 0) s[0] = r; }
    __syncthreads();
    return s[0];
}
__device__ __forceinline__ unsigned fkey(float f) {
    unsigned u = __float_as_uint(f);
    return (u & 0x80000000u) ? ~u : (u | 0x80000000u);
}
__device__ __forceinline__ float inv_fkey(unsigned u) {
    return __uint_as_float((u & 0x80000000u) ? (u ^ 0x80000000u) : ~u);
}
__device__ __forceinline__ uint32_t smem_addr_u32(const void* p) {
    return (uint32_t)__cvta_generic_to_shared(p);
}

// ---------------- init ------------------------------------------------------
__global__ void init_kernel() {
    int i = blockIdx.x * blockDim.x + threadIdx.x;   // grid covers 32768
    g_dmin[i] = 0xFFFFFFFFu;
    g_best2[i] = ~0ull;
    if (i < MCODES) { g_cnti[i] = 0; g_fill[i] = 0; }
    if (i == 0) {
        g_ncand = 0; g_nsurv = 0;
        g_en0max = 0; g_en1max = 0; g_dummy0 = 0; g_dummy1 = 0;
    }
}

// Fused: 2-way fp16 split of scale*v + per-row split norms + strict
// sequential fp32 sum-of-squares (reference rounding order). 2 rows/block.
__global__ void splitall_kernel(const float4* __restrict__ V,
                                __half* __restrict__ S, float scale,
                                float* __restrict__ sqout,
                                float* __restrict__ n0, float* __restrict__ n1,
                                unsigned* __restrict__ mx0, unsigned* __restrict__ mx1)
{
    __shared__ float rowv[1024];
    __shared__ float sw0[8], sw1[8];
    int tid = threadIdx.x;
    int i = blockIdx.x * 256 + tid;          // global float4 index
    int row = i >> 7, c4 = i & 127;
    int rl = tid >> 7;                       // row-local (0 or 1)
    float4 v = V[i];
    rowv[rl * 512 + c4 * 4 + 0] = v.x;
    rowv[rl * 512 + c4 * 4 + 1] = v.y;
    rowv[rl * 512 + c4 * 4 + 2] = v.z;
    rowv[rl * 512 + c4 * 4 + 3] = v.w;
    struct __align__(8) H4 { __half h[4]; } h0, h1;
    float vv[4] = {v.x * scale, v.y * scale, v.z * scale, v.w * scale};
    float s0 = 0.f, s1 = 0.f;
#pragma unroll
    for (int k = 0; k < 4; k++) {
        __half a = __float2half_rn(vv[k]);
        h0.h[k] = a;
        float r1 = vv[k] - __half2float(a);
        __half b = __float2half_rn(r1);
        h1.h[k] = b;
        float fa = __half2float(a), fb = __half2float(b);
        s0 += fa * fa;
        s1 += fb * fb;
    }
    size_t base = (size_t)row * 1024 + c4 * 4;
    *(uint2*)(S + base)       = *(uint2*)&h0;
    *(uint2*)(S + base + 512) = *(uint2*)&h1;
    // half-block norm reductions (warps 0-3 = row0, 4-7 = row1)
    s0 = warpReduceSum(s0);
    s1 = warpReduceSum(s1);
    int w = tid >> 5;
    if ((tid & 31) == 0) { sw0[w] = s0; sw1[w] = s1; }
    __syncthreads();
    if (tid == 0 || tid == 128) {
        int wb = rl * 4;
        float t0 = sw0[wb] + sw0[wb + 1] + sw0[wb + 2] + sw0[wb + 3];
        float t1 = sw1[wb] + sw1[wb + 1] + sw1[wb + 2] + sw1[wb + 3];
        float v0 = sqrtf(t0), v1 = sqrtf(t1);
        n0[row] = v0;
        n1[row] = v1;
        atomicMax(mx0, __float_as_uint(v0));
        atomicMax(mx1, __float_as_uint(v1));
        // strict sequential sum of squares (unscaled) for bucket exactness
        const float* p = rowv + rl * 512;
        float s = 0.f;
#pragma unroll 8
        for (int k = 0; k < 512; k++)
            s = __fadd_rn(s, __fmul_rn(p[k], p[k]));
        sqout[row] = s;
    }
}

// ---------------- mma / cp.async helpers ------------------------------------
template<bool USE_HALF>
__device__ __forceinline__ void mma16816t(float* d, const uint32_t* a,
                                          const uint32_t* b) {
    if (USE_HALF)
        asm volatile(
            "mma.sync.aligned.m16n8k16.row.col.f32.f16.f16.f32 "
            "{%0,%1,%2,%3}, {%4,%5,%6,%7}, {%8,%9}, {%0,%1,%2,%3};"
            : "+f"(d[0]), "+f"(d[1]), "+f"(d[2]), "+f"(d[3])
            : "r"(a[0]), "r"(a[1]), "r"(a[2]), "r"(a[3]), "r"(b[0]), "r"(b[1]));
    else
        asm volatile(
            "mma.sync.aligned.m16n8k16.row.col.f32.bf16.bf16.f32 "
            "{%0,%1,%2,%3}, {%4,%5,%6,%7}, {%8,%9}, {%0,%1,%2,%3};"
            : "+f"(d[0]), "+f"(d[1]), "+f"(d[2]), "+f"(d[3])
            : "r"(a[0]), "r"(a[1]), "r"(a[2]), "r"(a[3]), "r"(b[0]), "r"(b[1]));
}

__device__ __forceinline__ void cpasync16(uint32_t dst, const void* src) {
    asm volatile("cp.async.cg.shared.global [%0], [%1], 16;"
                 :: "r"(dst), "l"(src) : "memory");
}

__device__ __forceinline__ uint32_t swoff(int r, int c) {
    return ((uint32_t)(r >> 1) << 7) |
           ((uint32_t)((((r & 1) << 2) | c) ^ ((r >> 1) & 7)) << 4);
}

#define STAGE_BYTES 24576u

__device__ __forceinline__ void tcg_load(
    const uint16_t* A, int ldA, const uint16_t* B, int ldB,
    int rowBase, int colBase, uint32_t sbase, int st, int it, int tid)
{
    int kk = (it & 15) * 32;
    uint32_t base = sbase + (uint32_t)st * STAGE_BYTES;
#pragma unroll
    for (int j = 0; j < 4; j++) {          // A: 256 rows x 4 chunks
        int ch = tid + j * 256, r = ch >> 2, c = ch & 3;
        cpasync16(base + swoff(r, c),
                  A + (size_t)(rowBase + r) * ldA + kk + c * 8);
    }
#pragma unroll
    for (int j = 0; j < 2; j++) {          // B: 128 rows x 4 chunks
        int ch = tid + j * 256, r = ch >> 2, c = ch & 3;
        cpasync16(base + 16384 + swoff(r, c),
                  B + (size_t)(colBase + r) * ldB + kk + c * 8);
    }
    asm volatile("cp.async.commit_group;" ::: "memory");
}

// ---------------- 256x128 4-stage-pipelined tensor-core GEMM ----------------
// EPI: 1 = approx argmin + block-aggregated candidate append,
//      2 = fused CE partials, 3 = store bf16 C, 0 = store fp32 C.
template<int EPI, bool USE_HALF>
__global__ void __launch_bounds__(256) tcg256_kernel(
    const uint16_t* __restrict__ A, int ldA,
    const uint16_t* __restrict__ B, int ldB,
    float* __restrict__ C, int ldc)
{
    extern __shared__ __align__(16) unsigned char smem_s[];   // 4 x 24KB
    const int tid = threadIdx.x, lane = tid & 31, wid = tid >> 5;
    const int warp_m = wid & 3, warp_n = wid >> 2;   // 4m x 2n warps
    const int rowBase = blockIdx.y * 256;
    const int colBase = blockIdx.x * 128;
    const uint32_t sbase = smem_addr_u32(smem_s);

    float acc[4][8][4];
#pragma unroll
    for (int i = 0; i < 4; i++)
#pragma unroll
        for (int j = 0; j < 8; j++)
#pragma unroll
            for (int q = 0; q < 4; q++) acc[i][j][q] = 0.f;

    uint32_t offA[4][2], offB[4][2];
#pragma unroll
    for (int mt = 0; mt < 4; mt++) {
        int r = warp_m * 64 + mt * 16 + (lane & 15);
#pragma unroll
        for (int ks = 0; ks < 2; ks++)
            offA[mt][ks] = swoff(r, ks * 2 + (lane >> 4));
    }
#pragma unroll
    for (int p = 0; p < 4; p++) {
        int r = warp_n * 64 + p * 16 + (lane & 15);
#pragma unroll
        for (int ks = 0; ks < 2; ks++)
            offB[p][ks] = 16384u + swoff(r, ks * 2 + (lane >> 4));
    }

    const int nch = 16;   // K = 512
    tcg_load(A, ldA, B, ldB, rowBase, colBase, sbase, 0, 0, tid);
    tcg_load(A, ldA, B, ldB, rowBase, colBase, sbase, 1, 1, tid);
    tcg_load(A, ldA, B, ldB, rowBase, colBase, sbase, 2, 2, tid);

#pragma unroll 1
    for (int i = 0; i < nch; i++) {
        int rem = nch - 1 - i;
        if (rem >= 2)      asm volatile("cp.async.wait_group 2;" ::: "memory");
        else if (rem == 1) asm volatile("cp.async.wait_group 1;" ::: "memory");
        else               asm volatile("cp.async.wait_group 0;" ::: "memory");
        __syncthreads();
        if (i + 3 < nch)
            tcg_load(A, ldA, B, ldB, rowBase, colBase, sbase,
                     (i + 3) & 3, i + 3, tid);

        uint32_t stB = sbase + (uint32_t)(i & 3) * STAGE_BYTES;
#pragma unroll
        for (int ks = 0; ks < 2; ks++) {
            uint32_t af[4][4];
#pragma unroll
            for (int mt = 0; mt < 4; mt++) {
                uint32_t ad = stB + offA[mt][ks];
                asm volatile("ldmatrix.sync.aligned.m8n8.x4.shared.b16 {%0,%1,%2,%3}, [%4];"
                             : "=r"(af[mt][0]), "=r"(af[mt][1]),
                               "=r"(af[mt][2]), "=r"(af[mt][3]) : "r"(ad));
            }
            uint32_t bf[8][2];
#pragma unroll
            for (int p = 0; p < 4; p++) {
                uint32_t bd = stB + offB[p][ks];
                uint32_t q0, q1, q2, q3;
                asm volatile("ldmatrix.sync.aligned.m8n8.x4.shared.b16 {%0,%1,%2,%3}, [%4];"
                             : "=r"(q0), "=r"(q1), "=r"(q2), "=r"(q3) : "r"(bd));
                bf[2 * p][0] = q0; bf[2 * p][1] = q2;
                bf[2 * p + 1][0] = q1; bf[2 * p + 1][1] = q3;
            }
#pragma unroll
            for (int mt = 0; mt < 4; mt++)
#pragma unroll
                for (int nt = 0; nt < 8; nt++)
                    mma16816t<USE_HALF>(acc[mt][nt], af[mt], bf[nt]);
        }
    }

    if (EPI == 1) {
        // acc = 65536 * (x0 . e0); d_approx = fl(fl(esq+xsq) - 2*acc/65536).
        // Pass 1: group min + candidate count. Block scan. One atomicAdd/CTA.
        // Pass 2: write candidates at scanned offsets.
        const float INV = 1.0f / 65536.0f;
        const float e0m = __uint_as_float(g_en0max);
        const float e1m = __uint_as_float(g_en1max);
        const int rq = lane >> 2;
        float lims[8];
        int cnt = 0;
        __syncthreads();   // smem reuse safe (ldmatrix of last chunk done)
#pragma unroll
        for (int mt = 0; mt < 4; mt++) {
#pragma unroll
            for (int half = 0; half < 2; half++) {
                int row = rowBase + warp_m * 64 + mt * 16 + rq + half * 8;
                float xs = g_xsq[row];
                float W = 4.0f * INV * (g_xn0[row] * e1m +
                                        g_xn1[row] * (e0m + e1m)) + 1.3e-4f;
                float dmin = __int_as_float(0x7f800000);
                float dd[16];
#pragma unroll
                for (int nt = 0; nt < 8; nt++) {
#pragma unroll
                    for (int q = 0; q < 2; q++) {
                        int col = colBase + warp_n * 64 + nt * 8 + (lane & 3) * 2 + q;
                        float a = acc[mt][nt][half * 2 + q] * INV;
                        float t1 = __fadd_rn(g_esq[col], xs);
                        float d  = __fadd_rn(t1, -2.0f * a);
                        dd[nt * 2 + q] = d;
                        dmin = fminf(dmin, d);
                    }
                }
                dmin = fminf(dmin, __shfl_xor_sync(0xffffffffu, dmin, 1));
                dmin = fminf(dmin, __shfl_xor_sync(0xffffffffu, dmin, 2));
                if ((lane & 3) == 0) atomicMin(&g_dmin[row], fkey(dmin));
                float lim = dmin + W;
                lims[mt * 2 + half] = lim;
#pragma unroll
                for (int j = 0; j < 16; j++)
                    if (dd[j] <= lim) cnt++;
            }
        }
        // block scan of cnt (Hillis-Steele over 256 lanes in smem)
        int* sc = (int*)smem_s;
        sc[tid] = cnt;
        __syncthreads();
#pragma unroll
        for (int off = 1; off < 256; off <<= 1) {
            int add = (tid >= off) ? sc[tid - off] : 0;
            __syncthreads();
            sc[tid] += add;
            __syncthreads();
        }
        int* basep = sc + 256;
        if (tid == 255) *basep = atomicAdd(&g_ncand, sc[255]);
        __syncthreads();
        int mybase = *basep + sc[tid] - cnt;
        // pass 2: recompute + write
        int k = 0;
#pragma unroll
        for (int mt = 0; mt < 4; mt++) {
#pragma unroll
            for (int half = 0; half < 2; half++) {
                int row = rowBase + warp_m * 64 + mt * 16 + rq + half * 8;
                float xs = g_xsq[row];
                float lim = lims[mt * 2 + half];
#pragma unroll
                for (int nt = 0; nt < 8; nt++) {
#pragma unroll
                    for (int q = 0; q < 2; q++) {
                        int col = colBase + warp_n * 64 + nt * 8 + (lane & 3) * 2 + q;
                        float a = acc[mt][nt][half * 2 + q] * INV;
                        float t1 = __fadd_rn(g_esq[col], xs);
                        float d  = __fadd_rn(t1, -2.0f * a);
                        if (d <= lim) {
                            int p = mybase + k;
                            if (p < CAND_MAX) {
                                g_cand[p] = ((unsigned)row << 10) | (unsigned)col;
                                g_cdist[p] = d;
                            }
                            k++;
                        }
                    }
                }
            }
        }
    } else if (EPI == 2) {
        const int rq = lane >> 2;
#pragma unroll
        for (int mt = 0; mt < 4; mt++) {
#pragma unroll
            for (int half = 0; half < 2; half++) {
                int row = rowBase + warp_m * 64 + mt * 16 + rq + half * 8;
                int lab = g_labi[row];
                float mx = __int_as_float(0xff800000);
#pragma unroll
                for (int nt = 0; nt < 8; nt++)
#pragma unroll
                    for (int q = 0; q < 2; q++)
                        mx = fmaxf(mx, acc[mt][nt][half * 2 + q]);
                mx = fmaxf(mx, __shfl_xor_sync(0xffffffffu, mx, 1));
                mx = fmaxf(mx, __shfl_xor_sync(0xffffffffu, mx, 2));
                float s = 0.f;
#pragma unroll
                for (int nt = 0; nt < 8; nt++) {
#pragma unroll
                    for (int q = 0; q < 2; q++) {
                        float v = acc[mt][nt][half * 2 + q];
                        s += __expf(v - mx);
                        int col = colBase + warp_n * 64 + nt * 8 + (lane & 3) * 2 + q;
                        if (col == lab) g_labv[row] = v;
                    }
                }
                s += __shfl_xor_sync(0xffffffffu, s, 1);
                s += __shfl_xor_sync(0xffffffffu, s, 2);
                if ((lane & 3) == 0) {
                    int slab = blockIdx.x * 2 + warp_n;
                    g_pmax[(size_t)row * 16 + slab] = mx;
                    g_psum[(size_t)row * 16 + slab] = s;
                }
            }
        }
    } else if (EPI == 3) {
        __nv_bfloat16* Cb = (__nv_bfloat16*)C;
#pragma unroll
        for (int mt = 0; mt < 4; mt++) {
#pragma unroll
            for (int nt = 0; nt < 8; nt++) {
                int row0 = rowBase + warp_m * 64 + mt * 16 + (lane >> 2);
                int col  = colBase + warp_n * 64 + nt * 8 + (lane & 3) * 2;
                __nv_bfloat162 v0, v1;
                v0.x = __float2bfloat16(acc[mt][nt][0]);
                v0.y = __float2bfloat16(acc[mt][nt][1]);
                v1.x = __float2bfloat16(acc[mt][nt][2]);
                v1.y = __float2bfloat16(acc[mt][nt][3]);
                *(__nv_bfloat162*)(Cb + (size_t)row0 * ldc + col) = v0;
                *(__nv_bfloat162*)(Cb + (size_t)(row0 + 8) * ldc + col) = v1;
            }
        }
    } else {
#pragma unroll
        for (int mt = 0; mt < 4; mt++) {
#pragma unroll
            for (int nt = 0; nt < 8; nt++) {
                int row0 = rowBase + warp_m * 64 + mt * 16 + (lane >> 2);
                int col  = colBase + warp_n * 64 + nt * 8 + (lane & 3) * 2;
                *(float2*)(C + (size_t)row0 * ldc + col) =
                    make_float2(acc[mt][nt][0], acc[mt][nt][1]);
                *(float2*)(C + (size_t)(row0 + 8) * ldc + col) =
                    make_float2(acc[mt][nt][2], acc[mt][nt][3]);
            }
        }
    }
}

// ---------------- candidate filter + exact repass ----------------------------
__global__ void filter_kernel() {
    const float INV = 1.0f / 65536.0f;
    const float e0m = __uint_as_float(g_en0max);
    const float e1m = __uint_as_float(g_en1max);
    int n = min(g_ncand, CAND_MAX);
    for (int i = blockIdx.x * 256 + threadIdx.x; i < n; i += gridDim.x * 256) {
        unsigned pc = g_cand[i];
        int row = pc >> 10;
        float dm = inv_fkey(g_dmin[row]);
        float W = 4.0f * INV * (g_xn0[row] * e1m +
                                g_xn1[row] * (e0m + e1m)) + 1.3e-4f;
        if (g_cdist[i] <= dm + W) {
            int p = atomicAdd(&g_nsurv, 1);
            if (p < SURV_MAX) g_surv[p] = pc;
        }
    }
}

// exact fp32 distance for survivors; bucket-rounded argmin w/ low-index ties
__global__ void exact_kernel(const float* __restrict__ x,
                             const float* __restrict__ emb)
{
    int lane = threadIdx.x & 31;
    int wglob = (blockIdx.x * 256 + threadIdx.x) >> 5;
    int nwarp = (gridDim.x * 256) >> 5;
    int n = min(g_nsurv, SURV_MAX);
    for (int j = wglob; j < n; j += nwarp) {
        unsigned pc = g_surv[j];
        int row = pc >> 10, col = pc & 1023;
        const float* xr = x + (size_t)row * DDIM;
        const float* er = emb + (size_t)col * DDIM;
        float s = 0.f;
#pragma unroll 4
        for (int k = lane; k < DDIM; k += 32)
            s = fmaf(xr[k], er[k], s);
#pragma unroll
        for (int o = 16; o > 0; o >>= 1) s += __shfl_down_sync(0xffffffffu, s, o);
        if (lane == 0) {
            float t1 = __fadd_rn(g_esq[col], g_xsq[row]);
            float d  = __fadd_rn(t1, -2.0f * s);
            unsigned long long key =
                ((unsigned long long)fkey(d) << 32) | (unsigned)col;
            atomicMin(&g_best2[row], key);
        }
    }
}

// ---------------- weight transpose + bf16 convert ---------------------------
__global__ void wconv_kernel(const float* __restrict__ W,
                             __nv_bfloat16* __restrict__ Wt, int N)
{
    __shared__ float tile[32][33];
    int k0 = blockIdx.y * 32, n0 = blockIdx.x * 32;
    int tx = threadIdx.x & 31, ty = threadIdx.x >> 5;
#pragma unroll
    for (int i = 0; i < 32; i += 8)
        tile[ty + i][tx] = W[(size_t)(k0 + ty + i) * N + n0 + tx];
    __syncthreads();
#pragma unroll
    for (int i = 0; i < 32; i += 8)
        Wt[(size_t)(n0 + ty + i) * 512 + k0 + tx] = __float2bfloat16(tile[tx][ty + i]);
}

// ---------------- VQ bookkeeping: count / scan / scatter / dw-sum -----------
__global__ void countk_kernel() {
    int row = blockIdx.x * 256 + threadIdx.x;
    int idx = (int)(unsigned)(g_best2[row] & 0xFFFFFFFFull);
    atomicAdd(&g_cnti[idx], 1);
}

__global__ void prefix_kernel() {
    __shared__ int sh[MCODES];
    int t = threadIdx.x;
    int c = g_cnti[t];
    sh[t] = c;
    __syncthreads();
    for (int off = 1; off < MCODES; off <<= 1) {
        int add = (t >= off) ? sh[t - off] : 0;
        __syncthreads();
        sh[t] += add;
        __syncthreads();
    }
    g_off[t] = sh[t] - c;
    g_counts[t] = (float)c;
}

__global__ void scatter_kernel() {
    int row = blockIdx.x * 256 + threadIdx.x;
    int idx = (int)(unsigned)(g_best2[row] & 0xFFFFFFFFull);
    int p = atomicAdd(&g_fill[idx], 1);
    g_rows[g_off[idx] + p] = row;
}

// one block per code: sum assigned x rows, emit new_weight & new_embedding.
// out_emb/out_w are +1-float offset in packed output (4B aligned) -> scalar stores.
__global__ void dwsum_kernel(const float* __restrict__ x,
                             const float* __restrict__ ema_wt,
                             float* __restrict__ out_emb,
                             float* __restrict__ out_w)
{
    int m = blockIdx.x, t = threadIdx.x;
    int beg = g_off[m], cnt = g_cnti[m];
    float4 a0 = make_float4(0.f, 0.f, 0.f, 0.f);
    float4 a1 = make_float4(0.f, 0.f, 0.f, 0.f);
    int j = 0;
    for (; j + 1 < cnt; j += 2) {
        int r0 = g_rows[beg + j], r1 = g_rows[beg + j + 1];
        float4 v0 = ((const float4*)(x + (size_t)r0 * DDIM))[t];
        float4 v1 = ((const float4*)(x + (size_t)r1 * DDIM))[t];
        a0.x += v0.x; a0.y += v0.y; a0.z += v0.z; a0.w += v0.w;
        a1.x += v1.x; a1.y += v1.y; a1.z += v1.z; a1.w += v1.w;
    }
    if (j < cnt) {
        int r0 = g_rows[beg + j];
        float4 v0 = ((const float4*)(x + (size_t)r0 * DDIM))[t];
        a0.x += v0.x; a0.y += v0.y; a0.z += v0.z; a0.w += v0.w;
    }
    a0.x += a1.x; a0.y += a1.y; a0.z += a1.z; a0.w += a1.w;
    float4 w = ((const float4*)(ema_wt + (size_t)m * DDIM))[t];
    float nc = g_newc[m];
    float nw0 = 0.999f * w.x + 0.001f * a0.x;
    float nw1 = 0.999f * w.y + 0.001f * a0.y;
    float nw2 = 0.999f * w.z + 0.001f * a0.z;
    float nw3 = 0.999f * w.w + 0.001f * a0.w;
    size_t ob = (size_t)m * DDIM + t * 4;
    out_w[ob + 0] = nw0;
    out_w[ob + 1] = nw1;
    out_w[ob + 2] = nw2;
    out_w[ob + 3] = nw3;
    out_emb[ob + 0] = nw0 / nc;
    out_emb[ob + 1] = nw1 / nc;
    out_emb[ob + 2] = nw2 / nc;
    out_emb[ob + 3] = nw3 / nc;
}

// ---------------- post-VQ: gather, quantized_st, vq loss ---------------------
__global__ void postvq_kernel(const float* __restrict__ x,
                              const float* __restrict__ emb,
                              float* __restrict__ out_q)
{
    int row = blockIdx.x;
    int idx = (int)(unsigned)(g_best2[row] & 0xFFFFFFFFull);
    const float4* xr = (const float4*)(x   + (size_t)row * DDIM);
    const float4* er = (const float4*)(emb + (size_t)idx * DDIM);
    float4 xv = xr[threadIdx.x];
    float4 ev = er[threadIdx.x];
    float4 q;
    q.x = xv.x + (ev.x - xv.x);
    q.y = xv.y + (ev.y - xv.y);
    q.z = xv.z + (ev.z - xv.z);
    q.w = xv.w + (ev.w - xv.w);
    ((float4*)(out_q + (size_t)row * DDIM))[threadIdx.x] = q;

    float dx = xv.x - ev.x, dy = xv.y - ev.y, dz = xv.z - ev.z, dw2 = xv.w - ev.w;
    float s = dx * dx + dy * dy + dz * dz + dw2 * dw2;
    s = blockReduceSum(s);
    if (threadIdx.x == 0) g_vqrow[row] = 0.25f * s;
}

// ---------------- EMA count + perplexity ------------------------------------
__global__ void ema_kernel(const float* __restrict__ ema_count,
                           float* __restrict__ out_cnt,
                           float* __restrict__ out_perp)
{
    int m = threadIdx.x;
    float c = g_counts[m];
    float nc0 = 0.999f * ema_count[m] + 0.001f * c;
    float n = blockReduceSum(nc0);
    float newc = (nc0 + 1e-5f) / (n + (float)MCODES * 1e-5f) * n;
    out_cnt[m] = newc;
    g_newc[m] = newc;
    float p = c * (1.0f / (float)NROWS);
    float t = p * logf(p + 1e-10f);
    float s = blockReduceSum(t);
    if (m == 0) out_perp[0] = expf(-s);
}

// ---------------- LayerNorm + ReLU -> bf16 (templated input) ----------------
template<typename T>
__global__ void ln_relu_kernel(const T* __restrict__ X,
                               const float* __restrict__ g,
                               const float* __restrict__ b,
                               __nv_bfloat16* __restrict__ Y)
{
    constexpr int W = 512;
    constexpr int PER = 2;
    int row = blockIdx.x;
    const T* x = X + (size_t)row * W;
    float v[PER];
    float s = 0.f;
#pragma unroll
    for (int i = 0; i < PER; i++) { v[i] = (float)x[threadIdx.x + i * 256]; s += v[i]; }
    float mean = blockReduceSum(s) * (1.0f / W);
    float s2 = 0.f;
#pragma unroll
    for (int i = 0; i < PER; i++) { float d = v[i] - mean; s2 += d * d; }
    float var = blockReduceSum(s2) * (1.0f / W);
    float rstd = rsqrtf(var + 1e-5f);
#pragma unroll
    for (int i = 0; i < PER; i++) {
        int c = threadIdx.x + i * 256;
        float o = (v[i] - mean) * rstd * g[c] + b[c];
        Y[(size_t)row * W + c] = __float2bfloat16(fmaxf(o, 0.f));
    }
}

// ---------------- dtype detection + label convert ---------------------------
__global__ void detect_mask_kernel(const unsigned* __restrict__ m) {
    __shared__ int bad, gt1;
    if (threadIdx.x == 0) { bad = 0; gt1 = 0; }
    __syncthreads();
    for (int i = threadIdx.x; i < 8192; i += blockDim.x) {
        unsigned v = m[i];
        if (v > 1u) {
            atomicOr(&gt1, 1);
            if (v != 0x3F800000u) atomicOr(&bad, 1);
        }
    }
    __syncthreads();
    if (threadIdx.x == 0) g_mask_mode = (gt1 == 0) ? 0 : (bad ? 2 : 1);
}

__global__ void detect_lab_kernel(const unsigned* __restrict__ lab) {
    __shared__ int any_nz;
    if (threadIdx.x == 0) any_nz = 0;
    __syncthreads();
    for (int i = threadIdx.x; i < NROWS / 2; i += blockDim.x) {
        if (lab[2 * i + 1] != 0u) atomicOr(&any_nz, 1);
    }
    __syncthreads();
    if (threadIdx.x == 0) g_lab_mode = any_nz ? 0 : 1;
}

__global__ void labconv_kernel(const void* __restrict__ labels) {
    int i = blockIdx.x * 256 + threadIdx.x;
    g_labi[i] = g_lab_mode ? (int)((const long long*)labels)[i]
                           : ((const int*)labels)[i];
}

// ---------------- CE combine + final loss ------------------------------------
__global__ void ce_combine_kernel(const void* __restrict__ mask,
                                  float* __restrict__ out_loss)
{
    int row = blockIdx.x * 256 + threadIdx.x;
    const float* pm = g_pmax + (size_t)row * 16;
    const float* ps = g_psum + (size_t)row * 16;
    float M = __int_as_float(0xff800000);
#pragma unroll
    for (int i = 0; i < 16; i++) M = fmaxf(M, pm[i]);
    float S = 0.f;
#pragma unroll
    for (int i = 0; i < 16; i++) S += ps[i] * expf(pm[i] - M);
    float lse = M + logf(S);
    int mode = g_mask_mode;
    bool invalid;
    if (mode == 2)      invalid = ((const unsigned char*)mask)[row] != 0;
    else if (mode == 1) invalid = ((const float*)mask)[row] != 0.f;
    else                invalid = ((const int*)mask)[row] != 0;
    float ce = invalid ? 0.f : (lse - g_labv[row]);
    out_loss[row] = ce + g_vqrow[row];
}

// ---------------- launch -----------------------------------------------------
extern "C" void kernel_launch(void* const* d_in, const int* in_sizes, int n_in,
                              void* d_out, int out_size)
{
    const float* x         = (const float*)d_in[0];
    const void*  mask      = d_in[1];
    const void*  labels    = d_in[2];
    const float* emb       = (const float*)d_in[3];
    const float* ema_count = (const float*)d_in[4];
    const float* ema_wt    = (const float*)d_in[5];
    const float* ln1g      = (const float*)d_in[6];
    const float* ln1b      = (const float*)d_in[7];
    const float* W1        = (const float*)d_in[8];
    const float* ln2g      = (const float*)d_in[9];
    const float* ln2b      = (const float*)d_in[10];
    const float* W2        = (const float*)d_in[11];

    float* out      = (float*)d_out;
    float* out_q    = out;
    float* out_loss = out + (size_t)NROWS * DDIM;
    float* out_perp = out_loss + NROWS;
    float* out_emb  = out_perp + 1;
    float* out_cnt  = out_emb + (size_t)MCODES * DDIM;
    float* out_w    = out_cnt + MCODES;

    void *pa1, *phb, *pa2, *pxsq, *pesq, *pw1t, *pw2t, *pxs, *pes;
    void *pxn0, *pxn1, *pen0, *pen1, *pd0, *pd1, *pe0m, *pe1m;
    cudaGetSymbolAddress(&pa1, g_a1b);
    cudaGetSymbolAddress(&phb, g_hb);
    cudaGetSymbolAddress(&pa2, g_a2b);
    cudaGetSymbolAddress(&pxsq, g_xsq);
    cudaGetSymbolAddress(&pesq, g_esq);
    cudaGetSymbolAddress(&pw1t, g_w1t);
    cudaGetSymbolAddress(&pw2t, g_w2t);
    cudaGetSymbolAddress(&pxs, g_xs);
    cudaGetSymbolAddress(&pes, g_es);
    cudaGetSymbolAddress(&pxn0, g_xn0);
    cudaGetSymbolAddress(&pxn1, g_xn1);
    cudaGetSymbolAddress(&pen0, g_en0);
    cudaGetSymbolAddress(&pen1, g_en1);
    cudaGetSymbolAddress(&pd0, g_dummy0);
    cudaGetSymbolAddress(&pd1, g_dummy1);
    cudaGetSymbolAddress(&pe0m, g_en0max);
    cudaGetSymbolAddress(&pe1m, g_en1max);

    const int SMEM = 4 * 24576;   // 96 KB dynamic
    cudaFuncSetAttribute(tcg256_kernel<1, true>,
                         cudaFuncAttributeMaxDynamicSharedMemorySize, SMEM);
    cudaFuncSetAttribute(tcg256_kernel<3, false>,
                         cudaFuncAttributeMaxDynamicSharedMemorySize, SMEM);
    cudaFuncSetAttribute(tcg256_kernel<2, false>,
                         cudaFuncAttributeMaxDynamicSharedMemorySize, SMEM);

    // fork-join: stream B runs the decoder chain concurrently with VQ chain
    cudaStream_t sB;
    cudaStreamCreateWithFlags(&sB, cudaStreamNonBlocking);
    cudaEvent_t evF, evB;
    cudaEventCreateWithFlags(&evF, cudaEventDisableTiming);
    cudaEventCreateWithFlags(&evB, cudaEventDisableTiming);
    cudaEventRecord(evF, 0);
    cudaStreamWaitEvent(sB, evF, 0);

    // ===== stream B: decoder path + CE partials =====
    wconv_kernel<<<dim3(HDIM / 32, DDIM / 32), 256, 0, sB>>>(W1, (__nv_bfloat16*)pw1t, HDIM);
    wconv_kernel<<<dim3(MCODES / 32, HDIM / 32), 256, 0, sB>>>(W2, (__nv_bfloat16*)pw2t, MCODES);
    ln_relu_kernel<float><<<NROWS, 256, 0, sB>>>(x, ln1g, ln1b, (__nv_bfloat16*)pa1);
    tcg256_kernel<3, false><<<dim3(HDIM / 128, NROWS / 256), 256, SMEM, sB>>>(
        (const uint16_t*)pa1, 512, (const uint16_t*)pw1t, 512, (float*)phb, HDIM);
    ln_relu_kernel<__nv_bfloat16><<<NROWS, 256, 0, sB>>>((const __nv_bfloat16*)phb,
                                                         ln2g, ln2b, (__nv_bfloat16*)pa2);
    detect_mask_kernel<<<1, 256, 0, sB>>>((const unsigned*)mask);
    detect_lab_kernel<<<1, 256, 0, sB>>>((const unsigned*)labels);
    labconv_kernel<<<NROWS / 256, 256, 0, sB>>>(labels);
    tcg256_kernel<2, false><<<dim3(MCODES / 128, NROWS / 256), 256, SMEM, sB>>>(
        (const uint16_t*)pa2, 512, (const uint16_t*)pw2t, 512, nullptr, 0);
    cudaEventRecord(evB, sB);

    // ===== stream 0: VQ path (bucket-exact argmin + bookkeeping) =====
    init_kernel<<<128, 256>>>();
    splitall_kernel<<<MCODES / 2, 256>>>((const float4*)emb, (__half*)pes, 4096.0f,
                                         (float*)pesq, (float*)pen0, (float*)pen1,
                                         (unsigned*)pe0m, (unsigned*)pe1m);
    splitall_kernel<<<NROWS / 2, 256>>>((const float4*)x, (__half*)pxs, 16.0f,
                                        (float*)pxsq, (float*)pxn0, (float*)pxn1,
                                        (unsigned*)pd0, (unsigned*)pd1);
    tcg256_kernel<1, true><<<dim3(MCODES / 128, NROWS / 256), 256, SMEM>>>(
        (const uint16_t*)pxs, 1024, (const uint16_t*)pes, 1024, nullptr, 0);
    filter_kernel<<<256, 256>>>();
    exact_kernel<<<1024, 256>>>(x, emb);
    countk_kernel<<<NROWS / 256, 256>>>();
    prefix_kernel<<<1, MCODES>>>();
    ema_kernel<<<1, MCODES>>>(ema_count, out_cnt, out_perp);
    scatter_kernel<<<NROWS / 256, 256>>>();
    dwsum_kernel<<<MCODES, 128>>>(x, ema_wt, out_emb, out_w);
    postvq_kernel<<<NROWS, 128>>>(x, emb, out_q);

    // ===== join + final loss =====
    cudaStreamWaitEvent(0, evB, 0);
    ce_combine_kernel<<<NROWS / 256, 256>>>(mask, out_loss);
}

// round 15
// speedup vs baseline: 1.6414x; 1.1157x over previous
#include <cuda_runtime.h>
#include <cuda_bf16.h>
#include <cuda_fp16.h>
#include <cstdint>

#define NROWS 32768   // B*T
#define DDIM  512
#define HDIM  512
#define MCODES 1024
#define CAND_MAX (1 << 22)
#define SURV_MAX (1 << 20)

// ---------------- scratch (static device allocations; no cudaMalloc) -------
__device__ unsigned g_dmin[NROWS];                 // fkey(min d_approx) per row
__device__ unsigned long long g_best2[NROWS];      // final (fkey(d), col)
__device__ float g_counts[MCODES];
__device__ float g_esq[MCODES];
__device__ float g_xsq[NROWS];
__device__ float g_vqrow[NROWS];
__device__ float g_newc[MCODES];
__device__ int   g_mask_mode;
__device__ int   g_lab_mode;
__device__ int   g_labi[NROWS];
__device__ int   g_cnti[MCODES];
__device__ int   g_off[MCODES];
__device__ int   g_fill[MCODES];
__device__ int   g_rows[NROWS];
__device__ float g_pmax[(size_t)NROWS * 32];
__device__ float g_psum[(size_t)NROWS * 32];
__device__ float g_labv[NROWS];
__device__ float g_xn0[NROWS], g_xn1[NROWS];       // norms of scaled splits
__device__ float g_en0[MCODES], g_en1[MCODES];
__device__ unsigned g_en0max, g_en1max, g_dummy0, g_dummy1;
__device__ int   g_ncand, g_nsurv;
__device__ unsigned g_cand[CAND_MAX];
__device__ float    g_cdist[CAND_MAX];
__device__ unsigned g_surv[SURV_MAX];
__device__ __align__(16) __half g_xs[(size_t)NROWS * 1024];    // 16*x split
__device__ __align__(16) __half g_es[(size_t)MCODES * 1024];   // 4096*e split
__device__ __align__(16) __nv_bfloat16 g_a1b[(size_t)NROWS * DDIM];
__device__ __align__(16) __nv_bfloat16 g_a2b[(size_t)NROWS * HDIM];
__device__ __align__(16) __nv_bfloat16 g_hb[(size_t)NROWS * HDIM];
__device__ __align__(16) __nv_bfloat16 g_w1t[(size_t)HDIM * DDIM];
__device__ __align__(16) __nv_bfloat16 g_w2t[(size_t)MCODES * HDIM];

// ---------------- reduction helpers ----------------------------------------
__device__ __forceinline__ float warpReduceSum(float v) {
#pragma unroll
    for (int o = 16; o > 0; o >>= 1) v += __shfl_down_sync(0xffffffffu, v, o);
    return v;
}
__device__ __forceinline__ float blockReduceSum(float v) {
    __shared__ float s[32];
    __syncthreads();
    v = warpReduceSum(v);
    int lane = threadIdx.x & 31, w = threadIdx.x >> 5;
    if (lane == 0) s[w] = v;
    __syncthreads();
    int nw = blockDim.x >> 5;
    float r = (threadIdx.x < nw) ? s[threadIdx.x] : 0.f;
    if (w == 0) { r = warpReduceSum(r); if (lane == 0) s[0] = r; }
    __syncthreads();
    return s[0];
}
__device__ __forceinline__ unsigned fkey(float f) {
    unsigned u = __float_as_uint(f);
    return (u & 0x80000000u) ? ~u : (u | 0x80000000u);
}
__device__ __forceinline__ float inv_fkey(unsigned u) {
    return __uint_as_float((u & 0x80000000u) ? (u ^ 0x80000000u) : ~u);
}
__device__ __forceinline__ uint32_t smem_addr_u32(const void* p) {
    return (uint32_t)__cvta_generic_to_shared(p);
}

// ---------------- init ------------------------------------------------------
__global__ void init_kernel() {
    int i = blockIdx.x * blockDim.x + threadIdx.x;   // grid covers 32768
    g_dmin[i] = 0xFFFFFFFFu;
    g_best2[i] = ~0ull;
    if (i < MCODES) { g_cnti[i] = 0; g_fill[i] = 0; }
    if (i == 0) {
        g_ncand = 0; g_nsurv = 0;
        g_en0max = 0; g_en1max = 0; g_dummy0 = 0; g_dummy1 = 0;
    }
}

// Fused: 2-way fp16 split of scale*v + per-row split norms + strict
// sequential fp32 sum-of-squares (reference rounding order). 2 rows/block.
__global__ void splitall_kernel(const float4* __restrict__ V,
                                __half* __restrict__ S, float scale,
                                float* __restrict__ sqout,
                                float* __restrict__ n0, float* __restrict__ n1,
                                unsigned* __restrict__ mx0, unsigned* __restrict__ mx1)
{
    __shared__ float rowv[1024];
    __shared__ float sw0[8], sw1[8];
    int tid = threadIdx.x;
    int i = blockIdx.x * 256 + tid;          // global float4 index
    int row = i >> 7, c4 = i & 127;
    int rl = tid >> 7;                       // row-local (0 or 1)
    float4 v = V[i];
    rowv[rl * 512 + c4 * 4 + 0] = v.x;
    rowv[rl * 512 + c4 * 4 + 1] = v.y;
    rowv[rl * 512 + c4 * 4 + 2] = v.z;
    rowv[rl * 512 + c4 * 4 + 3] = v.w;
    struct __align__(8) H4 { __half h[4]; } h0, h1;
    float vv[4] = {v.x * scale, v.y * scale, v.z * scale, v.w * scale};
    float s0 = 0.f, s1 = 0.f;
#pragma unroll
    for (int k = 0; k < 4; k++) {
        __half a = __float2half_rn(vv[k]);
        h0.h[k] = a;
        float r1 = vv[k] - __half2float(a);
        __half b = __float2half_rn(r1);
        h1.h[k] = b;
        float fa = __half2float(a), fb = __half2float(b);
        s0 += fa * fa;
        s1 += fb * fb;
    }
    size_t base = (size_t)row * 1024 + c4 * 4;
    *(uint2*)(S + base)       = *(uint2*)&h0;
    *(uint2*)(S + base + 512) = *(uint2*)&h1;
    s0 = warpReduceSum(s0);
    s1 = warpReduceSum(s1);
    int w = tid >> 5;
    if ((tid & 31) == 0) { sw0[w] = s0; sw1[w] = s1; }
    __syncthreads();
    if (tid == 0 || tid == 128) {
        int wb = rl * 4;
        float t0 = sw0[wb] + sw0[wb + 1] + sw0[wb + 2] + sw0[wb + 3];
        float t1 = sw1[wb] + sw1[wb + 1] + sw1[wb + 2] + sw1[wb + 3];
        float v0 = sqrtf(t0), v1 = sqrtf(t1);
        n0[row] = v0;
        n1[row] = v1;
        atomicMax(mx0, __float_as_uint(v0));
        atomicMax(mx1, __float_as_uint(v1));
        const float* p = rowv + rl * 512;
        float s = 0.f;
#pragma unroll 8
        for (int k = 0; k < 512; k++)
            s = __fadd_rn(s, __fmul_rn(p[k], p[k]));
        sqout[row] = s;
    }
}

// ---------------- mma / cp.async helpers ------------------------------------
template<bool USE_HALF>
__device__ __forceinline__ void mma16816t(float* d, const uint32_t* a,
                                          const uint32_t* b) {
    if (USE_HALF)
        asm volatile(
            "mma.sync.aligned.m16n8k16.row.col.f32.f16.f16.f32 "
            "{%0,%1,%2,%3}, {%4,%5,%6,%7}, {%8,%9}, {%0,%1,%2,%3};"
            : "+f"(d[0]), "+f"(d[1]), "+f"(d[2]), "+f"(d[3])
            : "r"(a[0]), "r"(a[1]), "r"(a[2]), "r"(a[3]), "r"(b[0]), "r"(b[1]));
    else
        asm volatile(
            "mma.sync.aligned.m16n8k16.row.col.f32.bf16.bf16.f32 "
            "{%0,%1,%2,%3}, {%4,%5,%6,%7}, {%8,%9}, {%0,%1,%2,%3};"
            : "+f"(d[0]), "+f"(d[1]), "+f"(d[2]), "+f"(d[3])
            : "r"(a[0]), "r"(a[1]), "r"(a[2]), "r"(a[3]), "r"(b[0]), "r"(b[1]));
}

__device__ __forceinline__ void cpasync16(uint32_t dst, const void* src) {
    asm volatile("cp.async.cg.shared.global [%0], [%1], 16;"
                 :: "r"(dst), "l"(src) : "memory");
}

__device__ __forceinline__ uint32_t swoff(int r, int c) {
    return ((uint32_t)(r >> 1) << 7) |
           ((uint32_t)((((r & 1) << 2) | c) ^ ((r >> 1) & 7)) << 4);
}

#define STAGE_BYTES 16384u   // A 8KB + B 8KB (128x128 tile, K-chunk 32)

__device__ __forceinline__ void tcg_load(
    const uint16_t* A, int ldA, const uint16_t* B, int ldB,
    int rowBase, int colBase, uint32_t sbase, int st, int it, int tid)
{
    int kk = (it & 15) * 32;
    uint32_t base = sbase + (uint32_t)st * STAGE_BYTES;
#pragma unroll
    for (int j = 0; j < 2; j++) {          // A: 128 rows x 4 chunks
        int ch = tid + j * 256, r = ch >> 2, c = ch & 3;
        cpasync16(base + swoff(r, c),
                  A + (size_t)(rowBase + r) * ldA + kk + c * 8);
    }
#pragma unroll
    for (int j = 0; j < 2; j++) {          // B: 128 rows x 4 chunks
        int ch = tid + j * 256, r = ch >> 2, c = ch & 3;
        cpasync16(base + 8192 + swoff(r, c),
                  B + (size_t)(colBase + r) * ldB + kk + c * 8);
    }
    asm volatile("cp.async.commit_group;" ::: "memory");
}

// ---------------- 128x128 4-stage tensor-core GEMM, 2 CTAs/SM ---------------
// 8 warps = 2m x 4n; warp tile 64x32.
// EPI: 1 = approx argmin + block-aggregated candidate append,
//      2 = fused CE partials, 3 = store bf16 C, 0 = store fp32 C.
template<int EPI, bool USE_HALF>
__global__ void __launch_bounds__(256, 2) tcg128_kernel(
    const uint16_t* __restrict__ A, int ldA,
    const uint16_t* __restrict__ B, int ldB,
    float* __restrict__ C, int ldc)
{
    extern __shared__ __align__(16) unsigned char smem_s[];   // 4 x 16KB
    const int tid = threadIdx.x, lane = tid & 31, wid = tid >> 5;
    const int warp_m = wid & 1, warp_n = wid >> 1;   // 2m x 4n warps
    const int rowBase = blockIdx.y * 128;
    const int colBase = blockIdx.x * 128;
    const uint32_t sbase = smem_addr_u32(smem_s);

    float acc[4][4][4];
#pragma unroll
    for (int i = 0; i < 4; i++)
#pragma unroll
        for (int j = 0; j < 4; j++)
#pragma unroll
            for (int q = 0; q < 4; q++) acc[i][j][q] = 0.f;

    uint32_t offA[4][2], offB[2][2];
#pragma unroll
    for (int mt = 0; mt < 4; mt++) {
        int r = warp_m * 64 + mt * 16 + (lane & 15);
#pragma unroll
        for (int ks = 0; ks < 2; ks++)
            offA[mt][ks] = swoff(r, ks * 2 + (lane >> 4));
    }
#pragma unroll
    for (int p = 0; p < 2; p++) {
        int r = warp_n * 32 + p * 16 + (lane & 15);
#pragma unroll
        for (int ks = 0; ks < 2; ks++)
            offB[p][ks] = 8192u + swoff(r, ks * 2 + (lane >> 4));
    }

    const int nch = 16;   // K = 512
    tcg_load(A, ldA, B, ldB, rowBase, colBase, sbase, 0, 0, tid);
    tcg_load(A, ldA, B, ldB, rowBase, colBase, sbase, 1, 1, tid);
    tcg_load(A, ldA, B, ldB, rowBase, colBase, sbase, 2, 2, tid);

#pragma unroll 1
    for (int i = 0; i < nch; i++) {
        int rem = nch - 1 - i;
        if (rem >= 2)      asm volatile("cp.async.wait_group 2;" ::: "memory");
        else if (rem == 1) asm volatile("cp.async.wait_group 1;" ::: "memory");
        else               asm volatile("cp.async.wait_group 0;" ::: "memory");
        __syncthreads();
        if (i + 3 < nch)
            tcg_load(A, ldA, B, ldB, rowBase, colBase, sbase,
                     (i + 3) & 3, i + 3, tid);

        uint32_t stB = sbase + (uint32_t)(i & 3) * STAGE_BYTES;
#pragma unroll
        for (int ks = 0; ks < 2; ks++) {
            uint32_t af[4][4];
#pragma unroll
            for (int mt = 0; mt < 4; mt++) {
                uint32_t ad = stB + offA[mt][ks];
                asm volatile("ldmatrix.sync.aligned.m8n8.x4.shared.b16 {%0,%1,%2,%3}, [%4];"
                             : "=r"(af[mt][0]), "=r"(af[mt][1]),
                               "=r"(af[mt][2]), "=r"(af[mt][3]) : "r"(ad));
            }
            uint32_t bf[4][2];
#pragma unroll
            for (int p = 0; p < 2; p++) {
                uint32_t bd = stB + offB[p][ks];
                uint32_t q0, q1, q2, q3;
                asm volatile("ldmatrix.sync.aligned.m8n8.x4.shared.b16 {%0,%1,%2,%3}, [%4];"
                             : "=r"(q0), "=r"(q1), "=r"(q2), "=r"(q3) : "r"(bd));
                bf[2 * p][0] = q0; bf[2 * p][1] = q2;
                bf[2 * p + 1][0] = q1; bf[2 * p + 1][1] = q3;
            }
#pragma unroll
            for (int mt = 0; mt < 4; mt++)
#pragma unroll
                for (int nt = 0; nt < 4; nt++)
                    mma16816t<USE_HALF>(acc[mt][nt], af[mt], bf[nt]);
        }
    }

    if (EPI == 1) {
        // acc = 65536 * (x0 . e0); d_approx = fl(fl(esq+xsq) - 2*acc/65536).
        const float INV = 1.0f / 65536.0f;
        const float e0m = __uint_as_float(g_en0max);
        const float e1m = __uint_as_float(g_en1max);
        const int rq = lane >> 2;
        float lims[8];
        int cnt = 0;
        __syncthreads();
#pragma unroll
        for (int mt = 0; mt < 4; mt++) {
#pragma unroll
            for (int half = 0; half < 2; half++) {
                int row = rowBase + warp_m * 64 + mt * 16 + rq + half * 8;
                float xs = g_xsq[row];
                float W = 4.0f * INV * (g_xn0[row] * e1m +
                                        g_xn1[row] * (e0m + e1m)) + 1.3e-4f;
                float dmin = __int_as_float(0x7f800000);
                float dd[8];
#pragma unroll
                for (int nt = 0; nt < 4; nt++) {
#pragma unroll
                    for (int q = 0; q < 2; q++) {
                        int col = colBase + warp_n * 32 + nt * 8 + (lane & 3) * 2 + q;
                        float a = acc[mt][nt][half * 2 + q] * INV;
                        float t1 = __fadd_rn(g_esq[col], xs);
                        float d  = __fadd_rn(t1, -2.0f * a);
                        dd[nt * 2 + q] = d;
                        dmin = fminf(dmin, d);
                    }
                }
                dmin = fminf(dmin, __shfl_xor_sync(0xffffffffu, dmin, 1));
                dmin = fminf(dmin, __shfl_xor_sync(0xffffffffu, dmin, 2));
                if ((lane & 3) == 0) atomicMin(&g_dmin[row], fkey(dmin));
                float lim = dmin + W;
                lims[mt * 2 + half] = lim;
#pragma unroll
                for (int j = 0; j < 8; j++)
                    if (dd[j] <= lim) cnt++;
            }
        }
        int* sc = (int*)smem_s;
        sc[tid] = cnt;
        __syncthreads();
#pragma unroll
        for (int off = 1; off < 256; off <<= 1) {
            int add = (tid >= off) ? sc[tid - off] : 0;
            __syncthreads();
            sc[tid] += add;
            __syncthreads();
        }
        int* basep = sc + 256;
        if (tid == 255) *basep = atomicAdd(&g_ncand, sc[255]);
        __syncthreads();
        int mybase = *basep + sc[tid] - cnt;
        int k = 0;
#pragma unroll
        for (int mt = 0; mt < 4; mt++) {
#pragma unroll
            for (int half = 0; half < 2; half++) {
                int row = rowBase + warp_m * 64 + mt * 16 + rq + half * 8;
                float xs = g_xsq[row];
                float lim = lims[mt * 2 + half];
#pragma unroll
                for (int nt = 0; nt < 4; nt++) {
#pragma unroll
                    for (int q = 0; q < 2; q++) {
                        int col = colBase + warp_n * 32 + nt * 8 + (lane & 3) * 2 + q;
                        float a = acc[mt][nt][half * 2 + q] * INV;
                        float t1 = __fadd_rn(g_esq[col], xs);
                        float d  = __fadd_rn(t1, -2.0f * a);
                        if (d <= lim) {
                            int p = mybase + k;
                            if (p < CAND_MAX) {
                                g_cand[p] = ((unsigned)row << 10) | (unsigned)col;
                                g_cdist[p] = d;
                            }
                            k++;
                        }
                    }
                }
            }
        }
    } else if (EPI == 2) {
        // fused CE partials: per 32-col slab (max, sum-exp) + label logit
        const int rq = lane >> 2;
#pragma unroll
        for (int mt = 0; mt < 4; mt++) {
#pragma unroll
            for (int half = 0; half < 2; half++) {
                int row = rowBase + warp_m * 64 + mt * 16 + rq + half * 8;
                int lab = g_labi[row];
                float mx = __int_as_float(0xff800000);
#pragma unroll
                for (int nt = 0; nt < 4; nt++)
#pragma unroll
                    for (int q = 0; q < 2; q++)
                        mx = fmaxf(mx, acc[mt][nt][half * 2 + q]);
                mx = fmaxf(mx, __shfl_xor_sync(0xffffffffu, mx, 1));
                mx = fmaxf(mx, __shfl_xor_sync(0xffffffffu, mx, 2));
                float s = 0.f;
#pragma unroll
                for (int nt = 0; nt < 4; nt++) {
#pragma unroll
                    for (int q = 0; q < 2; q++) {
                        float v = acc[mt][nt][half * 2 + q];
                        s += __expf(v - mx);
                        int col = colBase + warp_n * 32 + nt * 8 + (lane & 3) * 2 + q;
                        if (col == lab) g_labv[row] = v;
                    }
                }
                s += __shfl_xor_sync(0xffffffffu, s, 1);
                s += __shfl_xor_sync(0xffffffffu, s, 2);
                if ((lane & 3) == 0) {
                    int slab = blockIdx.x * 4 + warp_n;   // 32 slabs of 32
                    g_pmax[(size_t)row * 32 + slab] = mx;
                    g_psum[(size_t)row * 32 + slab] = s;
                }
            }
        }
    } else if (EPI == 3) {
        __nv_bfloat16* Cb = (__nv_bfloat16*)C;
#pragma unroll
        for (int mt = 0; mt < 4; mt++) {
#pragma unroll
            for (int nt = 0; nt < 4; nt++) {
                int row0 = rowBase + warp_m * 64 + mt * 16 + (lane >> 2);
                int col  = colBase + warp_n * 32 + nt * 8 + (lane & 3) * 2;
                __nv_bfloat162 v0, v1;
                v0.x = __float2bfloat16(acc[mt][nt][0]);
                v0.y = __float2bfloat16(acc[mt][nt][1]);
                v1.x = __float2bfloat16(acc[mt][nt][2]);
                v1.y = __float2bfloat16(acc[mt][nt][3]);
                *(__nv_bfloat162*)(Cb + (size_t)row0 * ldc + col) = v0;
                *(__nv_bfloat162*)(Cb + (size_t)(row0 + 8) * ldc + col) = v1;
            }
        }
    } else {
#pragma unroll
        for (int mt = 0; mt < 4; mt++) {
#pragma unroll
            for (int nt = 0; nt < 4; nt++) {
                int row0 = rowBase + warp_m * 64 + mt * 16 + (lane >> 2);
                int col  = colBase + warp_n * 32 + nt * 8 + (lane & 3) * 2;
                *(float2*)(C + (size_t)row0 * ldc + col) =
                    make_float2(acc[mt][nt][0], acc[mt][nt][1]);
                *(float2*)(C + (size_t)(row0 + 8) * ldc + col) =
                    make_float2(acc[mt][nt][2], acc[mt][nt][3]);
            }
        }
    }
}

// ---------------- candidate filter + exact repass ----------------------------
__global__ void filter_kernel() {
    const float INV = 1.0f / 65536.0f;
    const float e0m = __uint_as_float(g_en0max);
    const float e1m = __uint_as_float(g_en1max);
    int n = min(g_ncand, CAND_MAX);
    for (int i = blockIdx.x * 256 + threadIdx.x; i < n; i += gridDim.x * 256) {
        unsigned pc = g_cand[i];
        int row = pc >> 10;
        float dm = inv_fkey(g_dmin[row]);
        float W = 4.0f * INV * (g_xn0[row] * e1m +
                                g_xn1[row] * (e0m + e1m)) + 1.3e-4f;
        if (g_cdist[i] <= dm + W) {
            int p = atomicAdd(&g_nsurv, 1);
            if (p < SURV_MAX) g_surv[p] = pc;
        }
    }
}

// exact fp32 distance for survivors; bucket-rounded argmin w/ low-index ties
__global__ void exact_kernel(const float* __restrict__ x,
                             const float* __restrict__ emb)
{
    int lane = threadIdx.x & 31;
    int wglob = (blockIdx.x * 256 + threadIdx.x) >> 5;
    int nwarp = (gridDim.x * 256) >> 5;
    int n = min(g_nsurv, SURV_MAX);
    for (int j = wglob; j < n; j += nwarp) {
        unsigned pc = g_surv[j];
        int row = pc >> 10, col = pc & 1023;
        const float* xr = x + (size_t)row * DDIM;
        const float* er = emb + (size_t)col * DDIM;
        float s = 0.f;
#pragma unroll 4
        for (int k = lane; k < DDIM; k += 32)
            s = fmaf(xr[k], er[k], s);
#pragma unroll
        for (int o = 16; o > 0; o >>= 1) s += __shfl_down_sync(0xffffffffu, s, o);
        if (lane == 0) {
            float t1 = __fadd_rn(g_esq[col], g_xsq[row]);
            float d  = __fadd_rn(t1, -2.0f * s);
            unsigned long long key =
                ((unsigned long long)fkey(d) << 32) | (unsigned)col;
            atomicMin(&g_best2[row], key);
        }
    }
}

// ---------------- weight transpose + bf16 convert ---------------------------
__global__ void wconv_kernel(const float* __restrict__ W,
                             __nv_bfloat16* __restrict__ Wt, int N)
{
    __shared__ float tile[32][33];
    int k0 = blockIdx.y * 32, n0 = blockIdx.x * 32;
    int tx = threadIdx.x & 31, ty = threadIdx.x >> 5;
#pragma unroll
    for (int i = 0; i < 32; i += 8)
        tile[ty + i][tx] = W[(size_t)(k0 + ty + i) * N + n0 + tx];
    __syncthreads();
#pragma unroll
    for (int i = 0; i < 32; i += 8)
        Wt[(size_t)(n0 + ty + i) * 512 + k0 + tx] = __float2bfloat16(tile[tx][ty + i]);
}

// ---------------- VQ bookkeeping: count / scan / scatter / dw-sum -----------
__global__ void countk_kernel() {
    int row = blockIdx.x * 256 + threadIdx.x;
    int idx = (int)(unsigned)(g_best2[row] & 0xFFFFFFFFull);
    atomicAdd(&g_cnti[idx], 1);
}

__global__ void prefix_kernel() {
    __shared__ int sh[MCODES];
    int t = threadIdx.x;
    int c = g_cnti[t];
    sh[t] = c;
    __syncthreads();
    for (int off = 1; off < MCODES; off <<= 1) {
        int add = (t >= off) ? sh[t - off] : 0;
        __syncthreads();
        sh[t] += add;
        __syncthreads();
    }
    g_off[t] = sh[t] - c;
    g_counts[t] = (float)c;
}

__global__ void scatter_kernel() {
    int row = blockIdx.x * 256 + threadIdx.x;
    int idx = (int)(unsigned)(g_best2[row] & 0xFFFFFFFFull);
    int p = atomicAdd(&g_fill[idx], 1);
    g_rows[g_off[idx] + p] = row;
}

// one block per code: sum assigned x rows, emit new_weight & new_embedding.
// out_emb/out_w are +1-float offset in packed output (4B aligned) -> scalar stores.
__global__ void dwsum_kernel(const float* __restrict__ x,
                             const float* __restrict__ ema_wt,
                             float* __restrict__ out_emb,
                             float* __restrict__ out_w)
{
    int m = blockIdx.x, t = threadIdx.x;
    int beg = g_off[m], cnt = g_cnti[m];
    float4 a0 = make_float4(0.f, 0.f, 0.f, 0.f);
    float4 a1 = make_float4(0.f, 0.f, 0.f, 0.f);
    int j = 0;
    for (; j + 1 < cnt; j += 2) {
        int r0 = g_rows[beg + j], r1 = g_rows[beg + j + 1];
        float4 v0 = ((const float4*)(x + (size_t)r0 * DDIM))[t];
        float4 v1 = ((const float4*)(x + (size_t)r1 * DDIM))[t];
        a0.x += v0.x; a0.y += v0.y; a0.z += v0.z; a0.w += v0.w;
        a1.x += v1.x; a1.y += v1.y; a1.z += v1.z; a1.w += v1.w;
    }
    if (j < cnt) {
        int r0 = g_rows[beg + j];
        float4 v0 = ((const float4*)(x + (size_t)r0 * DDIM))[t];
        a0.x += v0.x; a0.y += v0.y; a0.z += v0.z; a0.w += v0.w;
    }
    a0.x += a1.x; a0.y += a1.y; a0.z += a1.z; a0.w += a1.w;
    float4 w = ((const float4*)(ema_wt + (size_t)m * DDIM))[t];
    float nc = g_newc[m];
    float nw0 = 0.999f * w.x + 0.001f * a0.x;
    float nw1 = 0.999f * w.y + 0.001f * a0.y;
    float nw2 = 0.999f * w.z + 0.001f * a0.z;
    float nw3 = 0.999f * w.w + 0.001f * a0.w;
    size_t ob = (size_t)m * DDIM + t * 4;
    out_w[ob + 0] = nw0;
    out_w[ob + 1] = nw1;
    out_w[ob + 2] = nw2;
    out_w[ob + 3] = nw3;
    out_emb[ob + 0] = nw0 / nc;
    out_emb[ob + 1] = nw1 / nc;
    out_emb[ob + 2] = nw2 / nc;
    out_emb[ob + 3] = nw3 / nc;
}

// ---------------- post-VQ: gather, quantized_st, vq loss ---------------------
__global__ void postvq_kernel(const float* __restrict__ x,
                              const float* __restrict__ emb,
                              float* __restrict__ out_q)
{
    int row = blockIdx.x;
    int idx = (int)(unsigned)(g_best2[row] & 0xFFFFFFFFull);
    const float4* xr = (const float4*)(x   + (size_t)row * DDIM);
    const float4* er = (const float4*)(emb + (size_t)idx * DDIM);
    float4 xv = xr[threadIdx.x];
    float4 ev = er[threadIdx.x];
    float4 q;
    q.x = xv.x + (ev.x - xv.x);
    q.y = xv.y + (ev.y - xv.y);
    q.z = xv.z + (ev.z - xv.z);
    q.w = xv.w + (ev.w - xv.w);
    ((float4*)(out_q + (size_t)row * DDIM))[threadIdx.x] = q;

    float dx = xv.x - ev.x, dy = xv.y - ev.y, dz = xv.z - ev.z, dw2 = xv.w - ev.w;
    float s = dx * dx + dy * dy + dz * dz + dw2 * dw2;
    s = blockReduceSum(s);
    if (threadIdx.x == 0) g_vqrow[row] = 0.25f * s;
}

// ---------------- EMA count + perplexity ------------------------------------
__global__ void ema_kernel(const float* __restrict__ ema_count,
                           float* __restrict__ out_cnt,
                           float* __restrict__ out_perp)
{
    int m = threadIdx.x;
    float c = g_counts[m];
    float nc0 = 0.999f * ema_count[m] + 0.001f * c;
    float n = blockReduceSum(nc0);
    float newc = (nc0 + 1e-5f) / (n + (float)MCODES * 1e-5f) * n;
    out_cnt[m] = newc;
    g_newc[m] = newc;
    float p = c * (1.0f / (float)NROWS);
    float t = p * logf(p + 1e-10f);
    float s = blockReduceSum(t);
    if (m == 0) out_perp[0] = expf(-s);
}

// ---------------- LayerNorm + ReLU -> bf16 (templated input) ----------------
template<typename T>
__global__ void ln_relu_kernel(const T* __restrict__ X,
                               const float* __restrict__ g,
                               const float* __restrict__ b,
                               __nv_bfloat16* __restrict__ Y)
{
    constexpr int W = 512;
    constexpr int PER = 2;
    int row = blockIdx.x;
    const T* x = X + (size_t)row * W;
    float v[PER];
    float s = 0.f;
#pragma unroll
    for (int i = 0; i < PER; i++) { v[i] = (float)x[threadIdx.x + i * 256]; s += v[i]; }
    float mean = blockReduceSum(s) * (1.0f / W);
    float s2 = 0.f;
#pragma unroll
    for (int i = 0; i < PER; i++) { float d = v[i] - mean; s2 += d * d; }
    float var = blockReduceSum(s2) * (1.0f / W);
    float rstd = rsqrtf(var + 1e-5f);
#pragma unroll
    for (int i = 0; i < PER; i++) {
        int c = threadIdx.x + i * 256;
        float o = (v[i] - mean) * rstd * g[c] + b[c];
        Y[(size_t)row * W + c] = __float2bfloat16(fmaxf(o, 0.f));
    }
}

// ---------------- dtype detection + label convert ---------------------------
__global__ void detect_mask_kernel(const unsigned* __restrict__ m) {
    __shared__ int bad, gt1;
    if (threadIdx.x == 0) { bad = 0; gt1 = 0; }
    __syncthreads();
    for (int i = threadIdx.x; i < 8192; i += blockDim.x) {
        unsigned v = m[i];
        if (v > 1u) {
            atomicOr(&gt1, 1);
            if (v != 0x3F800000u) atomicOr(&bad, 1);
        }
    }
    __syncthreads();
    if (threadIdx.x == 0) g_mask_mode = (gt1 == 0) ? 0 : (bad ? 2 : 1);
}

__global__ void detect_lab_kernel(const unsigned* __restrict__ lab) {
    __shared__ int any_nz;
    if (threadIdx.x == 0) any_nz = 0;
    __syncthreads();
    for (int i = threadIdx.x; i < NROWS / 2; i += blockDim.x) {
        if (lab[2 * i + 1] != 0u) atomicOr(&any_nz, 1);
    }
    __syncthreads();
    if (threadIdx.x == 0) g_lab_mode = any_nz ? 0 : 1;
}

__global__ void labconv_kernel(const void* __restrict__ labels) {
    int i = blockIdx.x * 256 + threadIdx.x;
    g_labi[i] = g_lab_mode ? (int)((const long long*)labels)[i]
                           : ((const int*)labels)[i];
}

// ---------------- CE combine + final loss ------------------------------------
__global__ void ce_combine_kernel(const void* __restrict__ mask,
                                  float* __restrict__ out_loss)
{
    int row = blockIdx.x * 256 + threadIdx.x;
    const float* pm = g_pmax + (size_t)row * 32;
    const float* ps = g_psum + (size_t)row * 32;
    float M = __int_as_float(0xff800000);
#pragma unroll
    for (int i = 0; i < 32; i++) M = fmaxf(M, pm[i]);
    float S = 0.f;
#pragma unroll
    for (int i = 0; i < 32; i++) S += ps[i] * expf(pm[i] - M);
    float lse = M + logf(S);
    int mode = g_mask_mode;
    bool invalid;
    if (mode == 2)      invalid = ((const unsigned char*)mask)[row] != 0;
    else if (mode == 1) invalid = ((const float*)mask)[row] != 0.f;
    else                invalid = ((const int*)mask)[row] != 0;
    float ce = invalid ? 0.f : (lse - g_labv[row]);
    out_loss[row] = ce + g_vqrow[row];
}

// ---------------- launch -----------------------------------------------------
extern "C" void kernel_launch(void* const* d_in, const int* in_sizes, int n_in,
                              void* d_out, int out_size)
{
    const float* x         = (const float*)d_in[0];
    const void*  mask      = d_in[1];
    const void*  labels    = d_in[2];
    const float* emb       = (const float*)d_in[3];
    const float* ema_count = (const float*)d_in[4];
    const float* ema_wt    = (const float*)d_in[5];
    const float* ln1g      = (const float*)d_in[6];
    const float* ln1b      = (const float*)d_in[7];
    const float* W1        = (const float*)d_in[8];
    const float* ln2g      = (const float*)d_in[9];
    const float* ln2b      = (const float*)d_in[10];
    const float* W2        = (const float*)d_in[11];

    float* out      = (float*)d_out;
    float* out_q    = out;
    float* out_loss = out + (size_t)NROWS * DDIM;
    float* out_perp = out_loss + NROWS;
    float* out_emb  = out_perp + 1;
    float* out_cnt  = out_emb + (size_t)MCODES * DDIM;
    float* out_w    = out_cnt + MCODES;

    void *pa1, *phb, *pa2, *pxsq, *pesq, *pw1t, *pw2t, *pxs, *pes;
    void *pxn0, *pxn1, *pen0, *pen1, *pd0, *pd1, *pe0m, *pe1m;
    cudaGetSymbolAddress(&pa1, g_a1b);
    cudaGetSymbolAddress(&phb, g_hb);
    cudaGetSymbolAddress(&pa2, g_a2b);
    cudaGetSymbolAddress(&pxsq, g_xsq);
    cudaGetSymbolAddress(&pesq, g_esq);
    cudaGetSymbolAddress(&pw1t, g_w1t);
    cudaGetSymbolAddress(&pw2t, g_w2t);
    cudaGetSymbolAddress(&pxs, g_xs);
    cudaGetSymbolAddress(&pes, g_es);
    cudaGetSymbolAddress(&pxn0, g_xn0);
    cudaGetSymbolAddress(&pxn1, g_xn1);
    cudaGetSymbolAddress(&pen0, g_en0);
    cudaGetSymbolAddress(&pen1, g_en1);
    cudaGetSymbolAddress(&pd0, g_dummy0);
    cudaGetSymbolAddress(&pd1, g_dummy1);
    cudaGetSymbolAddress(&pe0m, g_en0max);
    cudaGetSymbolAddress(&pe1m, g_en1max);

    const int SMEM = 4 * 16384;   // 64 KB dynamic; 2 CTAs/SM
    cudaFuncSetAttribute(tcg128_kernel<1, true>,
                         cudaFuncAttributeMaxDynamicSharedMemorySize, SMEM);
    cudaFuncSetAttribute(tcg128_kernel<3, false>,
                         cudaFuncAttributeMaxDynamicSharedMemorySize, SMEM);
    cudaFuncSetAttribute(tcg128_kernel<2, false>,
                         cudaFuncAttributeMaxDynamicSharedMemorySize, SMEM);

    // fork-join: stream B runs the decoder chain concurrently with VQ chain
    cudaStream_t sB;
    cudaStreamCreateWithFlags(&sB, cudaStreamNonBlocking);
    cudaEvent_t evF, evB;
    cudaEventCreateWithFlags(&evF, cudaEventDisableTiming);
    cudaEventCreateWithFlags(&evB, cudaEventDisableTiming);
    cudaEventRecord(evF, 0);
    cudaStreamWaitEvent(sB, evF, 0);

    // ===== stream B: decoder path + CE partials =====
    wconv_kernel<<<dim3(HDIM / 32, DDIM / 32), 256, 0, sB>>>(W1, (__nv_bfloat16*)pw1t, HDIM);
    wconv_kernel<<<dim3(MCODES / 32, HDIM / 32), 256, 0, sB>>>(W2, (__nv_bfloat16*)pw2t, MCODES);
    ln_relu_kernel<float><<<NROWS, 256, 0, sB>>>(x, ln1g, ln1b, (__nv_bfloat16*)pa1);
    tcg128_kernel<3, false><<<dim3(HDIM / 128, NROWS / 128), 256, SMEM, sB>>>(
        (const uint16_t*)pa1, 512, (const uint16_t*)pw1t, 512, (float*)phb, HDIM);
    ln_relu_kernel<__nv_bfloat16><<<NROWS, 256, 0, sB>>>((const __nv_bfloat16*)phb,
                                                         ln2g, ln2b, (__nv_bfloat16*)pa2);
    detect_mask_kernel<<<1, 256, 0, sB>>>((const unsigned*)mask);
    detect_lab_kernel<<<1, 256, 0, sB>>>((const unsigned*)labels);
    labconv_kernel<<<NROWS / 256, 256, 0, sB>>>(labels);
    tcg128_kernel<2, false><<<dim3(MCODES / 128, NROWS / 128), 256, SMEM, sB>>>(
        (const uint16_t*)pa2, 512, (const uint16_t*)pw2t, 512, nullptr, 0);
    cudaEventRecord(evB, sB);

    // ===== stream 0: VQ path (bucket-exact argmin + bookkeeping) =====
    init_kernel<<<128, 256>>>();
    splitall_kernel<<<MCODES / 2, 256>>>((const float4*)emb, (__half*)pes, 4096.0f,
                                         (float*)pesq, (float*)pen0, (float*)pen1,
                                         (unsigned*)pe0m, (unsigned*)pe1m);
    splitall_kernel<<<NROWS / 2, 256>>>((const float4*)x, (__half*)pxs, 16.0f,
                                        (float*)pxsq, (float*)pxn0, (float*)pxn1,
                                        (unsigned*)pd0, (unsigned*)pd1);
    tcg128_kernel<1, true><<<dim3(MCODES / 128, NROWS / 128), 256, SMEM>>>(
        (const uint16_t*)pxs, 1024, (const uint16_t*)pes, 1024, nullptr, 0);
    filter_kernel<<<256, 256>>>();
    exact_kernel<<<1024, 256>>>(x, emb);
    countk_kernel<<<NROWS / 256, 256>>>();
    prefix_kernel<<<1, MCODES>>>();
    ema_kernel<<<1, MCODES>>>(ema_count, out_cnt, out_perp);
    scatter_kernel<<<NROWS / 256, 256>>>();
    dwsum_kernel<<<MCODES, 128>>>(x, ema_wt, out_emb, out_w);
    postvq_kernel<<<NROWS, 128>>>(x, emb, out_q);

    // ===== join + final loss =====
    cudaStreamWaitEvent(0, evB, 0);
    ce_combine_kernel<<<NROWS / 256, 256>>>(mask, out_loss);
}